// round 8
// baseline (speedup 1.0000x reference)
#include <cuda_runtime.h>
#include <cstdint>

typedef unsigned long long u64;

#define TT 512
#define BB 64
#define DD 512
#define HH 512
#define G4 2048
#define NCTA 128

// ---------------------------------------------------------------------------
// Device-global scratch
// ---------------------------------------------------------------------------
__device__ float g_G[(size_t)2 * TT * G4 * BB];   // precomputed x@Wih^T + bias
__device__ float g_h[2][2][HH][BB];               // [buf][dir][k][b]
__device__ unsigned g_bar_count;
__device__ volatile unsigned g_bar_gen;
__device__ unsigned g_cnt[2];                     // per-direction arrival counters

// ---------------------------------------------------------------------------
// f32x2 packed helpers (sm_103a FFMA2)
// ---------------------------------------------------------------------------
__device__ __forceinline__ u64 pk2(float a, float b) {
    u64 r; asm("mov.b64 %0, {%1,%2};" : "=l"(r) : "f"(a), "f"(b)); return r;
}
__device__ __forceinline__ void fma2(u64& d, u64 a, u64 b) {
    asm("fma.rn.f32x2 %0, %1, %2, %0;" : "+l"(d) : "l"(a), "l"(b));
}
__device__ __forceinline__ float2 unpk(u64 v) {
    float2 r; asm("mov.b64 {%0,%1}, %2;" : "=f"(r.x), "=f"(r.y) : "l"(v)); return r;
}
__device__ __forceinline__ float sigf(float x)  { return 1.0f / (1.0f + __expf(-x)); }
__device__ __forceinline__ float tanhfast(float x) {
    return 2.0f / (1.0f + __expf(-2.0f * x)) - 1.0f;
}

__device__ __forceinline__ unsigned smem_u32(const void* p) {
    return (unsigned)__cvta_generic_to_shared(p);
}
__device__ __forceinline__ void cp16(unsigned dst, const void* src) {
    asm volatile("cp.async.cg.shared.global [%0], [%1], 16;" :: "r"(dst), "l"(src) : "memory");
}
__device__ __forceinline__ void cp_commit() {
    asm volatile("cp.async.commit_group;" ::: "memory");
}
__device__ __forceinline__ void cp_wait1() {
    asm volatile("cp.async.wait_group 1;" ::: "memory");
}

// ---------------------------------------------------------------------------
// Classic grid barrier (used ONCE at phase2 start)
// ---------------------------------------------------------------------------
__device__ __forceinline__ void grid_barrier() {
    __syncthreads();
    if (threadIdx.x == 0) {
        unsigned gen = g_bar_gen;
        __threadfence();
        if (atomicAdd(&g_bar_count, 1u) == NCTA - 1) {
            g_bar_count = 0;
            __threadfence();
            g_bar_gen = gen + 1;
        } else {
            while (g_bar_gen == gen) { }
        }
        __threadfence();
    }
    __syncthreads();
}

// ---------------------------------------------------------------------------
// Phase 1 (unchanged, known-good)
// ---------------------------------------------------------------------------
__global__ void __launch_bounds__(256) phase1_kernel(
    const float* __restrict__ x,
    const float* __restrict__ Wf, const float* __restrict__ Wr,
    const float* __restrict__ bif, const float* __restrict__ bhf,
    const float* __restrict__ bir, const float* __restrict__ bhr)
{
    __shared__ __align__(16) float Wt[32][132];
    __shared__ __align__(16) float Xt[32][68];

    const int tid = threadIdx.x;
    const int n0  = blockIdx.x * 128;
    const int s   = blockIdx.y;
    const int dir = blockIdx.z;
    const int tt  = dir ? (TT - 1 - s) : s;
    const float* __restrict__ W = dir ? Wr : Wf;

    const int bg = tid & 15;
    const int ng = tid >> 4;

    u64 acc[8][2];
#pragma unroll
    for (int i = 0; i < 8; i++) { acc[i][0] = 0ull; acc[i][1] = 0ull; }

    const float* xbase = x + (size_t)tt * BB * DD;

    for (int d0 = 0; d0 < DD; d0 += 32) {
        __syncthreads();
#pragma unroll
        for (int i = 0; i < 4; i++) {
            int lin = tid + 256 * i;
            int n = lin >> 3, kq = lin & 7;
            float4 w = *(const float4*)(W + (size_t)(n0 + n) * DD + d0 + kq * 4);
            Wt[kq*4+0][n] = w.x; Wt[kq*4+1][n] = w.y;
            Wt[kq*4+2][n] = w.z; Wt[kq*4+3][n] = w.w;
        }
#pragma unroll
        for (int i = 0; i < 2; i++) {
            int lin = tid + 256 * i;
            int b = lin >> 3, kq = lin & 7;
            float4 v = *(const float4*)(xbase + (size_t)b * DD + d0 + kq * 4);
            Xt[kq*4+0][b] = v.x; Xt[kq*4+1][b] = v.y;
            Xt[kq*4+2][b] = v.z; Xt[kq*4+3][b] = v.w;
        }
        __syncthreads();
#pragma unroll 8
        for (int k = 0; k < 32; k++) {
            float4 xa = *(const float4*)&Xt[k][bg * 4];
            u64 xv0 = pk2(xa.x, xa.y);
            u64 xv1 = pk2(xa.z, xa.w);
            float wv[8];
            *(float4*)&wv[0] = *(const float4*)&Wt[k][ng * 8];
            *(float4*)&wv[4] = *(const float4*)&Wt[k][ng * 8 + 4];
#pragma unroll
            for (int i = 0; i < 8; i++) {
                u64 w = pk2(wv[i], wv[i]);
                fma2(acc[i][0], w, xv0);
                fma2(acc[i][1], w, xv1);
            }
        }
    }

    const float* bi = dir ? bir : bif;
    const float* bh = dir ? bhr : bhf;
    float* Gp = g_G + ((size_t)(dir * TT + s) * G4 + n0 + ng * 8) * BB;
#pragma unroll
    for (int i = 0; i < 8; i++) {
        int n = n0 + ng * 8 + i;
        float bsum = bi[n] + bh[n];
        float2 p0 = unpk(acc[i][0]);
        float2 p1 = unpk(acc[i][1]);
        float4 o = make_float4(p0.x + bsum, p0.y + bsum, p1.x + bsum, p1.y + bsum);
        *(float4*)(Gp + (size_t)i * BB + bg * 4) = o;
    }
}

// ---------------------------------------------------------------------------
// Phase 2 v6: direction-interleaved persistent recurrence.
// 128 CTAs x 512 threads. CTA owns 4 hidden units in BOTH directions
// (16 gate rows per dir). Per step: fwd block then rev block. Split
// arrive/wait monotonic barriers per direction hide the h-propagation
// latency under the other direction's compute. h read via __ldcg from L2
// (no smem staging). G/mask double-buffered via cp.async, one block early.
//
// SMEM floats: Ws[2][512][16]=16384 | gbuf[8][16][64]=8192 |
//   Gs[2][2][16][64]=4096 | Ms[2][2][64]=256 | csm[2][4][64]=512 |
//   hosm[2][64][4]=512  -> total 29952 floats = 119808 B
// ---------------------------------------------------------------------------
#define SMW   0
#define SMGB  16384
#define SMGS  24576
#define SMMS  28672
#define SMC   28928
#define SMH   29440
#define SMTOT 29952

__device__ __forceinline__ void prefetchG(float* Gs, float* Ms,
                                          const float* __restrict__ mask,
                                          int j0, int tid, int pdir, int ps)
{
    if (tid < 256) {
        int row = tid >> 4, off = tid & 15;
        int gate = row >> 2, u = row & 3;
        const float* src = g_G
            + ((size_t)(pdir * TT + ps) * G4 + gate * HH + j0 + u) * BB + off * 4;
        cp16(smem_u32(Gs + ((pdir * 2 + (ps & 1)) * 16 + row) * 64 + off * 4), src);
    } else if (tid < 272) {
        int mo = tid - 256;
        int tg = pdir ? (TT - 1 - ps) : ps;
        cp16(smem_u32(Ms + (pdir * 2 + (ps & 1)) * 64 + mo * 4),
             mask + (size_t)tg * BB + mo * 4);
    }
}

__global__ void __launch_bounds__(512) phase2_kernel(
    const float* __restrict__ Whf, const float* __restrict__ Whr,
    const float* __restrict__ mask, float* __restrict__ out)
{
    extern __shared__ __align__(16) float sm[];
    float* Ws   = sm + SMW;
    float* gbuf = sm + SMGB;
    float* Gs   = sm + SMGS;
    float* Ms   = sm + SMMS;
    float* csm  = sm + SMC;
    float* hosm = sm + SMH;

    const int tid = threadIdx.x;
    const int cid = blockIdx.x;
    const int j0  = cid * 4;                 // 4 hidden units per dir

    // --- init: Ws[dir][k][16] rows rl = gate*4+u ---------------------------
    for (int i = tid; i < 2 * 512 * 16; i += 512) {
        int dir = i >> 13;
        int rem = i & 8191;
        int k = rem >> 4, rl = rem & 15;
        int gate = rl >> 2, u = rl & 3;
        const float* Whh = dir ? Whr : Whf;
        sm[SMW + i] = Whh[(size_t)(gate * HH + j0 + u) * HH + k];
    }
    // zero state + h buffer 0 slice (512 = 2dir*4u*64b, one per thread)
    {
        int dir = tid >> 8, u = (tid >> 6) & 3, b = tid & 63;
        csm[tid] = 0.0f;
        hosm[tid] = 0.0f;
        g_h[0][dir][j0 + u][b] = 0.0f;
    }
    if (cid == 0 && tid == 0) { g_cnt[0] = 0; g_cnt[1] = 0; }
    __syncthreads();

    // prefetch G_f(0) + mask_f(0)  (group #0)
    prefetchG(Gs, Ms, mask, j0, tid, 0, 0);
    cp_commit();
    grid_barrier();   // counters reset + h zeros globally visible

    const int w    = tid >> 5;
    const int lane = tid & 31;
    const int kh   = w >> 1;                 // 0..7 (64-k chunk)
    const int bh   = w & 1;
    const int b    = bh * 32 + lane;

    for (int s = 0; s < TT; s++) {
        const int pb = s & 1, nb = pb ^ 1;
#pragma unroll 1
        for (int dir = 0; dir < 2; dir++) {
            // prefetch the NEXT block's G/mask (other direction)
            const int pdir = dir ^ 1;
            const int ps = (dir == 0) ? s : s + 1;
            if (ps < TT) prefetchG(Gs, Ms, mask, j0, tid, pdir, ps);
            cp_commit();
            cp_wait1();                      // own G/mask resident

            // wait: h[dir](s) published by all CTAs
            if (s > 0 && tid == 0) {
                unsigned target = (unsigned)(NCTA * s);
                while (*(volatile unsigned*)&g_cnt[dir] < target) { }
                __threadfence();
            }
            __syncthreads();

            // --- GEMM: 16 rows x 64 b x 512 k, h via L2 (ldcg) -------------
            u64 acc[8];
#pragma unroll
            for (int rp = 0; rp < 8; rp++) acc[rp] = 0ull;
            {
                const float* hp = &g_h[pb][dir][kh * 64][b];
                const float* wp = Ws + ((size_t)dir * 512 + kh * 64) * 16;
#pragma unroll 8
                for (int k = 0; k < 64; k++) {
                    float hv = __ldcg(hp + (size_t)k * 64);
                    u64 hd = pk2(hv, hv);
                    const float* wk = wp + (size_t)k * 16;
                    ulonglong2 w01 = *(const ulonglong2*)(wk);
                    ulonglong2 w23 = *(const ulonglong2*)(wk + 4);
                    ulonglong2 w45 = *(const ulonglong2*)(wk + 8);
                    ulonglong2 w67 = *(const ulonglong2*)(wk + 12);
                    fma2(acc[0], w01.x, hd); fma2(acc[1], w01.y, hd);
                    fma2(acc[2], w23.x, hd); fma2(acc[3], w23.y, hd);
                    fma2(acc[4], w45.x, hd); fma2(acc[5], w45.y, hd);
                    fma2(acc[6], w67.x, hd); fma2(acc[7], w67.y, hd);
                }
            }
            // partial write: gbuf[kh][row][b]
            {
                float* gb = gbuf + kh * 1024 + b;
#pragma unroll
                for (int rp = 0; rp < 8; rp++) {
                    float2 v = unpk(acc[rp]);
                    gb[(2 * rp) * 64]     = v.x;
                    gb[(2 * rp + 1) * 64] = v.y;
                }
            }
            __syncthreads();

            // --- epilogue: reduce 8 planes + G, gates, state ---------------
            if (tid < 256) {
                const int u = tid >> 6, eb = tid & 63;
                float pre[4];
#pragma unroll
                for (int g = 0; g < 4; g++) {
                    int row = g * 4 + u;
                    float p = Gs[((dir * 2 + (s & 1)) * 16 + row) * 64 + eb];
#pragma unroll
                    for (int q = 0; q < 8; q++)
                        p += gbuf[q * 1024 + row * 64 + eb];
                    pre[g] = p;
                }
                const float m = Ms[(dir * 2 + (s & 1)) * 64 + eb];
                float ig = sigf(pre[0]);
                float fg = sigf(pre[1]);
                float gg = tanhfast(pre[2]);
                float og = sigf(pre[3]);
                float c_old = csm[dir * 256 + u * 64 + eb];
                float c2 = fg * c_old + ig * gg;
                float h2 = og * tanhfast(c2);
                float c_new = c_old + m * (c2 - c_old);
                float h_old = hosm[dir * 256 + eb * 4 + u];
                float h_new = h_old + m * (h2 - h_old);
                csm[dir * 256 + u * 64 + eb] = c_new;
                hosm[dir * 256 + eb * 4 + u] = h_new;
                g_h[nb][dir][j0 + u][eb] = h_new;
            }
            __syncthreads();

            // output store (contiguous float4 per batch element)
            if (tid < 64) {
                const int tg = dir ? (TT - 1 - s) : s;
                *(float4*)&out[(size_t)tg * (BB * 1024) + (size_t)tid * 1024
                               + dir * HH + j0]
                    = *(const float4*)&hosm[dir * 256 + tid * 4];
            }

            // arrive: h[dir](s+1) published
            if (tid == 0) {
                __threadfence();
                atomicAdd(&g_cnt[dir], 1u);
            }
        }
    }
}

// ---------------------------------------------------------------------------
// Launch
// ---------------------------------------------------------------------------
extern "C" void kernel_launch(void* const* d_in, const int* in_sizes, int n_in,
                              void* d_out, int out_size) {
    const float* x_data = (const float*)d_in[0];
    const float* x_mask = (const float*)d_in[1];
    const float* Wih_f  = (const float*)d_in[2];
    const float* Whh_f  = (const float*)d_in[3];
    const float* bih_f  = (const float*)d_in[4];
    const float* bhh_f  = (const float*)d_in[5];
    const float* Wih_r  = (const float*)d_in[6];
    const float* Whh_r  = (const float*)d_in[7];
    const float* bih_r  = (const float*)d_in[8];
    const float* bhh_r  = (const float*)d_in[9];
    float* out = (float*)d_out;

    static bool attr_set = false;
    if (!attr_set) {
        cudaFuncSetAttribute(phase2_kernel,
                             cudaFuncAttributeMaxDynamicSharedMemorySize,
                             SMTOT * 4);
        attr_set = true;
    }

    dim3 g1(16, 512, 2);
    phase1_kernel<<<g1, 256>>>(x_data, Wih_f, Wih_r, bih_f, bhh_f, bih_r, bhh_r);
    phase2_kernel<<<NCTA, 512, SMTOT * 4>>>(Whh_f, Whh_r, x_mask, out);
}

// round 9
// speedup vs baseline: 1.0007x; 1.0007x over previous
#include <cuda_runtime.h>
#include <cstdint>

typedef unsigned long long u64;

#define TT 512
#define BB 64
#define DD 512
#define HH 512
#define G4 2048
#define NCTA 128

// ---------------------------------------------------------------------------
// Device-global scratch
// ---------------------------------------------------------------------------
__device__ float g_G[(size_t)2 * TT * G4 * BB];   // precomputed x@Wih^T + bias
__device__ float g_h[2][2][HH][BB];               // [buf][dir][k][b]
__device__ unsigned g_bar_count;
__device__ volatile unsigned g_bar_gen;
__device__ unsigned g_cnt[2];                     // per-direction arrival counters

// ---------------------------------------------------------------------------
// f32x2 packed helpers (sm_103a FFMA2)
// ---------------------------------------------------------------------------
__device__ __forceinline__ u64 pk2(float a, float b) {
    u64 r; asm("mov.b64 %0, {%1,%2};" : "=l"(r) : "f"(a), "f"(b)); return r;
}
__device__ __forceinline__ void fma2(u64& d, u64 a, u64 b) {
    asm("fma.rn.f32x2 %0, %1, %2, %0;" : "+l"(d) : "l"(a), "l"(b));
}
__device__ __forceinline__ float2 unpk(u64 v) {
    float2 r; asm("mov.b64 {%0,%1}, %2;" : "=f"(r.x), "=f"(r.y) : "l"(v)); return r;
}
__device__ __forceinline__ float sigf(float x)  { return 1.0f / (1.0f + __expf(-x)); }
__device__ __forceinline__ float tanhfast(float x) {
    return 2.0f / (1.0f + __expf(-2.0f * x)) - 1.0f;
}

__device__ __forceinline__ unsigned smem_u32(const void* p) {
    return (unsigned)__cvta_generic_to_shared(p);
}
__device__ __forceinline__ void cp16(unsigned dst, const void* src) {
    asm volatile("cp.async.cg.shared.global [%0], [%1], 16;" :: "r"(dst), "l"(src) : "memory");
}
__device__ __forceinline__ void cp_commit() {
    asm volatile("cp.async.commit_group;" ::: "memory");
}
__device__ __forceinline__ void cp_wait1() {
    asm volatile("cp.async.wait_group 1;" ::: "memory");
}

// ---------------------------------------------------------------------------
// Classic grid barrier (used ONCE at phase2 start)
// ---------------------------------------------------------------------------
__device__ __forceinline__ void grid_barrier() {
    __syncthreads();
    if (threadIdx.x == 0) {
        unsigned gen = g_bar_gen;
        __threadfence();
        if (atomicAdd(&g_bar_count, 1u) == NCTA - 1) {
            g_bar_count = 0;
            __threadfence();
            g_bar_gen = gen + 1;
        } else {
            while (g_bar_gen == gen) { }
        }
        __threadfence();
    }
    __syncthreads();
}

// ---------------------------------------------------------------------------
// Phase 1 (unchanged, known-good)
// ---------------------------------------------------------------------------
__global__ void __launch_bounds__(256) phase1_kernel(
    const float* __restrict__ x,
    const float* __restrict__ Wf, const float* __restrict__ Wr,
    const float* __restrict__ bif, const float* __restrict__ bhf,
    const float* __restrict__ bir, const float* __restrict__ bhr)
{
    __shared__ __align__(16) float Wt[32][132];
    __shared__ __align__(16) float Xt[32][68];

    const int tid = threadIdx.x;
    const int n0  = blockIdx.x * 128;
    const int s   = blockIdx.y;
    const int dir = blockIdx.z;
    const int tt  = dir ? (TT - 1 - s) : s;
    const float* __restrict__ W = dir ? Wr : Wf;

    const int bg = tid & 15;
    const int ng = tid >> 4;

    u64 acc[8][2];
#pragma unroll
    for (int i = 0; i < 8; i++) { acc[i][0] = 0ull; acc[i][1] = 0ull; }

    const float* xbase = x + (size_t)tt * BB * DD;

    for (int d0 = 0; d0 < DD; d0 += 32) {
        __syncthreads();
#pragma unroll
        for (int i = 0; i < 4; i++) {
            int lin = tid + 256 * i;
            int n = lin >> 3, kq = lin & 7;
            float4 w = *(const float4*)(W + (size_t)(n0 + n) * DD + d0 + kq * 4);
            Wt[kq*4+0][n] = w.x; Wt[kq*4+1][n] = w.y;
            Wt[kq*4+2][n] = w.z; Wt[kq*4+3][n] = w.w;
        }
#pragma unroll
        for (int i = 0; i < 2; i++) {
            int lin = tid + 256 * i;
            int b = lin >> 3, kq = lin & 7;
            float4 v = *(const float4*)(xbase + (size_t)b * DD + d0 + kq * 4);
            Xt[kq*4+0][b] = v.x; Xt[kq*4+1][b] = v.y;
            Xt[kq*4+2][b] = v.z; Xt[kq*4+3][b] = v.w;
        }
        __syncthreads();
#pragma unroll 8
        for (int k = 0; k < 32; k++) {
            float4 xa = *(const float4*)&Xt[k][bg * 4];
            u64 xv0 = pk2(xa.x, xa.y);
            u64 xv1 = pk2(xa.z, xa.w);
            float wv[8];
            *(float4*)&wv[0] = *(const float4*)&Wt[k][ng * 8];
            *(float4*)&wv[4] = *(const float4*)&Wt[k][ng * 8 + 4];
#pragma unroll
            for (int i = 0; i < 8; i++) {
                u64 w = pk2(wv[i], wv[i]);
                fma2(acc[i][0], w, xv0);
                fma2(acc[i][1], w, xv1);
            }
        }
    }

    const float* bi = dir ? bir : bif;
    const float* bh = dir ? bhr : bhf;
    float* Gp = g_G + ((size_t)(dir * TT + s) * G4 + n0 + ng * 8) * BB;
#pragma unroll
    for (int i = 0; i < 8; i++) {
        int n = n0 + ng * 8 + i;
        float bsum = bi[n] + bh[n];
        float2 p0 = unpk(acc[i][0]);
        float2 p1 = unpk(acc[i][1]);
        float4 o = make_float4(p0.x + bsum, p0.y + bsum, p1.x + bsum, p1.y + bsum);
        *(float4*)(Gp + (size_t)i * BB + bg * 4) = o;
    }
}

// ---------------------------------------------------------------------------
// Phase 2 v6: direction-interleaved persistent recurrence.
// 128 CTAs x 512 threads. CTA owns 4 hidden units in BOTH directions
// (16 gate rows per dir). Per step: fwd block then rev block. Split
// arrive/wait monotonic barriers per direction hide the h-propagation
// latency under the other direction's compute. h read via __ldcg from L2
// (no smem staging). G/mask double-buffered via cp.async, one block early.
//
// SMEM floats: Ws[2][512][16]=16384 | gbuf[8][16][64]=8192 |
//   Gs[2][2][16][64]=4096 | Ms[2][2][64]=256 | csm[2][4][64]=512 |
//   hosm[2][64][4]=512  -> total 29952 floats = 119808 B
// ---------------------------------------------------------------------------
#define SMW   0
#define SMGB  16384
#define SMGS  24576
#define SMMS  28672
#define SMC   28928
#define SMH   29440
#define SMTOT 29952

__device__ __forceinline__ void prefetchG(float* Gs, float* Ms,
                                          const float* __restrict__ mask,
                                          int j0, int tid, int pdir, int ps)
{
    if (tid < 256) {
        int row = tid >> 4, off = tid & 15;
        int gate = row >> 2, u = row & 3;
        const float* src = g_G
            + ((size_t)(pdir * TT + ps) * G4 + gate * HH + j0 + u) * BB + off * 4;
        cp16(smem_u32(Gs + ((pdir * 2 + (ps & 1)) * 16 + row) * 64 + off * 4), src);
    } else if (tid < 272) {
        int mo = tid - 256;
        int tg = pdir ? (TT - 1 - ps) : ps;
        cp16(smem_u32(Ms + (pdir * 2 + (ps & 1)) * 64 + mo * 4),
             mask + (size_t)tg * BB + mo * 4);
    }
}

__global__ void __launch_bounds__(512) phase2_kernel(
    const float* __restrict__ Whf, const float* __restrict__ Whr,
    const float* __restrict__ mask, float* __restrict__ out)
{
    extern __shared__ __align__(16) float sm[];
    float* Ws   = sm + SMW;
    float* gbuf = sm + SMGB;
    float* Gs   = sm + SMGS;
    float* Ms   = sm + SMMS;
    float* csm  = sm + SMC;
    float* hosm = sm + SMH;

    const int tid = threadIdx.x;
    const int cid = blockIdx.x;
    const int j0  = cid * 4;                 // 4 hidden units per dir

    // --- init: Ws[dir][k][16] rows rl = gate*4+u ---------------------------
    for (int i = tid; i < 2 * 512 * 16; i += 512) {
        int dir = i >> 13;
        int rem = i & 8191;
        int k = rem >> 4, rl = rem & 15;
        int gate = rl >> 2, u = rl & 3;
        const float* Whh = dir ? Whr : Whf;
        sm[SMW + i] = Whh[(size_t)(gate * HH + j0 + u) * HH + k];
    }
    // zero state + h buffer 0 slice (512 = 2dir*4u*64b, one per thread)
    {
        int dir = tid >> 8, u = (tid >> 6) & 3, b = tid & 63;
        csm[tid] = 0.0f;
        hosm[tid] = 0.0f;
        g_h[0][dir][j0 + u][b] = 0.0f;
    }
    if (cid == 0 && tid == 0) { g_cnt[0] = 0; g_cnt[1] = 0; }
    __syncthreads();

    // prefetch G_f(0) + mask_f(0)  (group #0)
    prefetchG(Gs, Ms, mask, j0, tid, 0, 0);
    cp_commit();
    grid_barrier();   // counters reset + h zeros globally visible

    const int w    = tid >> 5;
    const int lane = tid & 31;
    const int kh   = w >> 1;                 // 0..7 (64-k chunk)
    const int bh   = w & 1;
    const int b    = bh * 32 + lane;

    for (int s = 0; s < TT; s++) {
        const int pb = s & 1, nb = pb ^ 1;
#pragma unroll 1
        for (int dir = 0; dir < 2; dir++) {
            // prefetch the NEXT block's G/mask (other direction)
            const int pdir = dir ^ 1;
            const int ps = (dir == 0) ? s : s + 1;
            if (ps < TT) prefetchG(Gs, Ms, mask, j0, tid, pdir, ps);
            cp_commit();
            cp_wait1();                      // own G/mask resident

            // wait: h[dir](s) published by all CTAs
            if (s > 0 && tid == 0) {
                unsigned target = (unsigned)(NCTA * s);
                while (*(volatile unsigned*)&g_cnt[dir] < target) { }
                __threadfence();
            }
            __syncthreads();

            // --- GEMM: 16 rows x 64 b x 512 k, h via L2 (ldcg) -------------
            u64 acc[8];
#pragma unroll
            for (int rp = 0; rp < 8; rp++) acc[rp] = 0ull;
            {
                const float* hp = &g_h[pb][dir][kh * 64][b];
                const float* wp = Ws + ((size_t)dir * 512 + kh * 64) * 16;
#pragma unroll 8
                for (int k = 0; k < 64; k++) {
                    float hv = __ldcg(hp + (size_t)k * 64);
                    u64 hd = pk2(hv, hv);
                    const float* wk = wp + (size_t)k * 16;
                    ulonglong2 w01 = *(const ulonglong2*)(wk);
                    ulonglong2 w23 = *(const ulonglong2*)(wk + 4);
                    ulonglong2 w45 = *(const ulonglong2*)(wk + 8);
                    ulonglong2 w67 = *(const ulonglong2*)(wk + 12);
                    fma2(acc[0], w01.x, hd); fma2(acc[1], w01.y, hd);
                    fma2(acc[2], w23.x, hd); fma2(acc[3], w23.y, hd);
                    fma2(acc[4], w45.x, hd); fma2(acc[5], w45.y, hd);
                    fma2(acc[6], w67.x, hd); fma2(acc[7], w67.y, hd);
                }
            }
            // partial write: gbuf[kh][row][b]
            {
                float* gb = gbuf + kh * 1024 + b;
#pragma unroll
                for (int rp = 0; rp < 8; rp++) {
                    float2 v = unpk(acc[rp]);
                    gb[(2 * rp) * 64]     = v.x;
                    gb[(2 * rp + 1) * 64] = v.y;
                }
            }
            __syncthreads();

            // --- epilogue: reduce 8 planes + G, gates, state ---------------
            if (tid < 256) {
                const int u = tid >> 6, eb = tid & 63;
                float pre[4];
#pragma unroll
                for (int g = 0; g < 4; g++) {
                    int row = g * 4 + u;
                    float p = Gs[((dir * 2 + (s & 1)) * 16 + row) * 64 + eb];
#pragma unroll
                    for (int q = 0; q < 8; q++)
                        p += gbuf[q * 1024 + row * 64 + eb];
                    pre[g] = p;
                }
                const float m = Ms[(dir * 2 + (s & 1)) * 64 + eb];
                float ig = sigf(pre[0]);
                float fg = sigf(pre[1]);
                float gg = tanhfast(pre[2]);
                float og = sigf(pre[3]);
                float c_old = csm[dir * 256 + u * 64 + eb];
                float c2 = fg * c_old + ig * gg;
                float h2 = og * tanhfast(c2);
                float c_new = c_old + m * (c2 - c_old);
                float h_old = hosm[dir * 256 + eb * 4 + u];
                float h_new = h_old + m * (h2 - h_old);
                csm[dir * 256 + u * 64 + eb] = c_new;
                hosm[dir * 256 + eb * 4 + u] = h_new;
                g_h[nb][dir][j0 + u][eb] = h_new;
            }
            __syncthreads();

            // output store (contiguous float4 per batch element)
            if (tid < 64) {
                const int tg = dir ? (TT - 1 - s) : s;
                *(float4*)&out[(size_t)tg * (BB * 1024) + (size_t)tid * 1024
                               + dir * HH + j0]
                    = *(const float4*)&hosm[dir * 256 + tid * 4];
            }

            // arrive: h[dir](s+1) published
            if (tid == 0) {
                __threadfence();
                atomicAdd(&g_cnt[dir], 1u);
            }
        }
    }
}

// ---------------------------------------------------------------------------
// Launch
// ---------------------------------------------------------------------------
extern "C" void kernel_launch(void* const* d_in, const int* in_sizes, int n_in,
                              void* d_out, int out_size) {
    const float* x_data = (const float*)d_in[0];
    const float* x_mask = (const float*)d_in[1];
    const float* Wih_f  = (const float*)d_in[2];
    const float* Whh_f  = (const float*)d_in[3];
    const float* bih_f  = (const float*)d_in[4];
    const float* bhh_f  = (const float*)d_in[5];
    const float* Wih_r  = (const float*)d_in[6];
    const float* Whh_r  = (const float*)d_in[7];
    const float* bih_r  = (const float*)d_in[8];
    const float* bhh_r  = (const float*)d_in[9];
    float* out = (float*)d_out;

    static bool attr_set = false;
    if (!attr_set) {
        cudaFuncSetAttribute(phase2_kernel,
                             cudaFuncAttributeMaxDynamicSharedMemorySize,
                             SMTOT * 4);
        attr_set = true;
    }

    dim3 g1(16, 512, 2);
    phase1_kernel<<<g1, 256>>>(x_data, Wih_f, Wih_r, bih_f, bhh_f, bih_r, bhh_r);
    phase2_kernel<<<NCTA, 512, SMTOT * 4>>>(Whh_f, Whh_r, x_mask, out);
}

// round 11
// speedup vs baseline: 1.6950x; 1.6938x over previous
#include <cuda_runtime.h>
#include <cuda_bf16.h>
#include <cstdint>

typedef unsigned long long u64;
typedef unsigned u32;

#define TT 512
#define BB 64
#define DD 512
#define HH 512
#define G4 2048
#define NCTA 128

// ---------------- global scratch ----------------
__device__ float g_G[(size_t)2 * TT * G4 * BB];   // x@Wih^T + bias
__device__ u32 g_Afrag[NCTA][16384];              // W frags: [hl][mt][ks][lane][4]
__device__ u32 g_hfrag[2][2][32768];              // h frags: [buf][dir][ks][hl][n8t][lane][2]
__device__ unsigned g_bar_count;
__device__ volatile unsigned g_bar_gen;

// ---------------- helpers ----------------
__device__ __forceinline__ u64 pk2f(float a, float b) {
    u64 r; asm("mov.b64 %0, {%1,%2};" : "=l"(r) : "f"(a), "f"(b)); return r;
}
__device__ __forceinline__ void fma2(u64& d, u64 a, u64 b) {
    asm("fma.rn.f32x2 %0, %1, %2, %0;" : "+l"(d) : "l"(a), "l"(b));
}
__device__ __forceinline__ float2 unpk(u64 v) {
    float2 r; asm("mov.b64 {%0,%1}, %2;" : "=f"(r.x), "=f"(r.y) : "l"(v)); return r;
}
__device__ __forceinline__ float sigf(float x)  { return 1.0f / (1.0f + __expf(-x)); }
__device__ __forceinline__ float tanhfast(float x) {
    return 2.0f / (1.0f + __expf(-2.0f * x)) - 1.0f;
}
__device__ __forceinline__ unsigned smem_u32(const void* p) {
    return (unsigned)__cvta_generic_to_shared(p);
}
__device__ __forceinline__ void cp16(unsigned dst, const void* src) {
    asm volatile("cp.async.cg.shared.global [%0], [%1], 16;" :: "r"(dst), "l"(src) : "memory");
}
__device__ __forceinline__ void cp_commit() { asm volatile("cp.async.commit_group;" ::: "memory"); }
__device__ __forceinline__ void cp_wait0()  { asm volatile("cp.async.wait_group 0;" ::: "memory"); }

__device__ __forceinline__ void mbar_init(unsigned a, unsigned c) {
    asm volatile("mbarrier.init.shared.b64 [%0], %1;" :: "r"(a), "r"(c) : "memory");
}
__device__ __forceinline__ void mbar_expect_tx(unsigned a, unsigned b) {
    asm volatile("mbarrier.arrive.expect_tx.shared.b64 _, [%0], %1;" :: "r"(a), "r"(b) : "memory");
}
__device__ __forceinline__ void bulk_g2s(unsigned dst, const void* src, unsigned bytes, unsigned mb) {
    asm volatile("cp.async.bulk.shared::cta.global.mbarrier::complete_tx::bytes [%0], [%1], %2, [%3];"
                 :: "r"(dst), "l"(src), "r"(bytes), "r"(mb) : "memory");
}
__device__ __forceinline__ void mbar_wait(unsigned a, unsigned par) {
    asm volatile(
        "{\n\t.reg .pred P;\n\t"
        "WL_%=:\n\t"
        "mbarrier.try_wait.parity.acquire.cta.shared::cta.b64 P, [%0], %1, 0x989680;\n\t"
        "@P bra.uni WD_%=;\n\t"
        "bra.uni WL_%=;\n\t"
        "WD_%=:\n\t}"
        :: "r"(a), "r"(par) : "memory");
}

__device__ __forceinline__ void mma16816(float* c, const u32* a, u32 b0, u32 b1) {
    asm volatile(
        "mma.sync.aligned.m16n8k16.row.col.f32.bf16.bf16.f32 "
        "{%0,%1,%2,%3}, {%4,%5,%6,%7}, {%8,%9}, {%0,%1,%2,%3};"
        : "+f"(c[0]), "+f"(c[1]), "+f"(c[2]), "+f"(c[3])
        : "r"(a[0]), "r"(a[1]), "r"(a[2]), "r"(a[3]), "r"(b0), "r"(b1));
}

__device__ __forceinline__ u32 packbf2(float e0, float e1) {   // e0 -> low half
    __nv_bfloat162 v = __float22bfloat162_rn(make_float2(e0, e1));
    return *(u32*)&v;
}

__device__ __forceinline__ void grid_barrier() {
    __syncthreads();
    if (threadIdx.x == 0) {
        unsigned gen = g_bar_gen;
        __threadfence();
        if (atomicAdd(&g_bar_count, 1u) == NCTA - 1) {
            g_bar_count = 0; __threadfence(); g_bar_gen = gen + 1;
        } else { while (g_bar_gen == gen) { } }
        __threadfence();
    }
    __syncthreads();
}

// ---------------- Phase 1 (known-good fp32 FFMA2 GEMM) ----------------
__global__ void __launch_bounds__(256) phase1_kernel(
    const float* __restrict__ x,
    const float* __restrict__ Wf, const float* __restrict__ Wr,
    const float* __restrict__ bif, const float* __restrict__ bhf,
    const float* __restrict__ bir, const float* __restrict__ bhr)
{
    __shared__ __align__(16) float Wt[32][132];
    __shared__ __align__(16) float Xt[32][68];
    const int tid = threadIdx.x;
    const int n0  = blockIdx.x * 128;
    const int s   = blockIdx.y;
    const int dir = blockIdx.z;
    const int tt  = dir ? (TT - 1 - s) : s;
    const float* __restrict__ W = dir ? Wr : Wf;
    const int bg = tid & 15, ng = tid >> 4;
    u64 acc[8][2];
#pragma unroll
    for (int i = 0; i < 8; i++) { acc[i][0] = 0ull; acc[i][1] = 0ull; }
    const float* xbase = x + (size_t)tt * BB * DD;
    for (int d0 = 0; d0 < DD; d0 += 32) {
        __syncthreads();
#pragma unroll
        for (int i = 0; i < 4; i++) {
            int lin = tid + 256 * i, n = lin >> 3, kq = lin & 7;
            float4 w = *(const float4*)(W + (size_t)(n0 + n) * DD + d0 + kq * 4);
            Wt[kq*4+0][n] = w.x; Wt[kq*4+1][n] = w.y;
            Wt[kq*4+2][n] = w.z; Wt[kq*4+3][n] = w.w;
        }
#pragma unroll
        for (int i = 0; i < 2; i++) {
            int lin = tid + 256 * i, b = lin >> 3, kq = lin & 7;
            float4 v = *(const float4*)(xbase + (size_t)b * DD + d0 + kq * 4);
            Xt[kq*4+0][b] = v.x; Xt[kq*4+1][b] = v.y;
            Xt[kq*4+2][b] = v.z; Xt[kq*4+3][b] = v.w;
        }
        __syncthreads();
#pragma unroll 8
        for (int k = 0; k < 32; k++) {
            float4 xa = *(const float4*)&Xt[k][bg * 4];
            u64 xv0 = pk2f(xa.x, xa.y), xv1 = pk2f(xa.z, xa.w);
            float wv[8];
            *(float4*)&wv[0] = *(const float4*)&Wt[k][ng * 8];
            *(float4*)&wv[4] = *(const float4*)&Wt[k][ng * 8 + 4];
#pragma unroll
            for (int i = 0; i < 8; i++) {
                u64 w = pk2f(wv[i], wv[i]);
                fma2(acc[i][0], w, xv0); fma2(acc[i][1], w, xv1);
            }
        }
    }
    const float* bi = dir ? bir : bif;
    const float* bh = dir ? bhr : bhf;
    float* Gp = g_G + ((size_t)(dir * TT + s) * G4 + n0 + ng * 8) * BB;
#pragma unroll
    for (int i = 0; i < 8; i++) {
        int n = n0 + ng * 8 + i;
        float bs = bi[n] + bh[n];
        float2 p0 = unpk(acc[i][0]), p1 = unpk(acc[i][1]);
        *(float4*)(Gp + (size_t)i * BB + bg * 4) =
            make_float4(p0.x + bs, p0.y + bs, p1.x + bs, p1.y + bs);
    }
}

// ---------------- Prep: W fragment images + zero h frag buf0 ----------------
// A frag layout (u32): idx = (((hl*2+mt)*32+ks)*32+lane)*4 + reg
// reg0: m=mt*16+g      k=ks*16+2t    ; reg1: m+8 same k
// reg2: m=mt*16+g      k=ks*16+8+2t  ; reg3: m+8, k+8       (g=lane>>2, t=lane&3)
__global__ void __launch_bounds__(256) prep_kernel(
    const float* __restrict__ Whf, const float* __restrict__ Whr)
{
    const int cid = blockIdx.x;
    const int dir = cid >> 6;
    const int j0  = (cid & 63) * 8;
    const float* __restrict__ W = dir ? Whr : Whf;
    for (int idx = threadIdx.x; idx < 16384; idx += 256) {
        int hl = idx >> 13;
        int rem = idx & 8191;
        int mt = rem >> 12;
        int ks = (rem >> 7) & 31;
        int lane = (rem >> 2) & 31;
        int reg = rem & 3;
        int g = lane >> 2, t = lane & 3;
        int m = mt * 16 + g + ((reg & 1) ? 8 : 0);
        int k = ks * 16 + 2 * t + ((reg & 2) ? 8 : 0);
        int gate = m >> 3, u = m & 7;
        const float* wr = W + (size_t)(gate * HH + j0 + u) * HH + k;
        float w0 = wr[0], w1 = wr[1];
        if (hl == 0) {
            g_Afrag[cid][idx] = packbf2(w0, w1);
        } else {
            float r0 = w0 - __bfloat162float(__float2bfloat16(w0));
            float r1 = w1 - __bfloat162float(__float2bfloat16(w1));
            g_Afrag[cid][idx] = packbf2(r0, r1);
        }
    }
    // zero h frag buffer 0 (both dirs): 65536 u32 over 128*256 threads
    {
        int i = blockIdx.x * 256 + threadIdx.x;
        u64* Z = (u64*)&g_hfrag[0][0][0];
        if (i < 32768) Z[i] = 0ull;
    }
}

// ---------------- Phase 2: persistent mma.sync recurrence -------------------
// SMEM bytes: Afrag 65536 | hfrag 131072 | Gs[32][68]f 8704 | Dex[2][32][66]f
// 16896 | cs 2112 | hs 2112 | mask 256 | mbar 64  -> 226816 total
#define SB_AF  0
#define SB_HF  65536
#define SB_GS  196608
#define SB_DEX 205312
#define SB_CS  222208
#define SB_HS  224320
#define SB_MK  226432
#define SB_MB  226688
#define SMEM2  226816

// h frag layout (u32): idx = (((ks*2+hl)*8+n8t)*32+lane)*2 + reg
//   element B[k][n]: n8t=n/8, g=n%8, t=(k%8)/2, pp=k%2, reg=(k%16)/8, ks=k/16
//   lane = g*4+t;  pair packed (k even -> low half)
__global__ void __launch_bounds__(256) phase2_kernel(
    const float* __restrict__ mask, float* __restrict__ out)
{
    extern __shared__ __align__(16) char smem[];
    float* Gs  = (float*)(smem + SB_GS);
    float* Dex = (float*)(smem + SB_DEX);
    float* cs  = (float*)(smem + SB_CS);
    float* hs  = (float*)(smem + SB_HS);
    float* Ms  = (float*)(smem + SB_MK);
    const unsigned af_sa = smem_u32(smem + SB_AF);
    const unsigned hf_sa = smem_u32(smem + SB_HF);
    const unsigned gs_sa = smem_u32(smem + SB_GS);
    const unsigned mk_sa = smem_u32(smem + SB_MK);
    const unsigned MB    = smem_u32(smem + SB_MB);

    const int tid = threadIdx.x;
    const int cid = blockIdx.x;
    const int dir = cid >> 6;
    const int j0  = (cid & 63) * 8;

    // init: Afrag -> smem, zero state, mbars
    if (tid < 8) mbar_init(MB + tid * 8, 1);
    for (int i = tid; i < 528; i += 256) { cs[i] = 0.0f; hs[i] = 0.0f; }
#pragma unroll
    for (int r = 0; r < 16; r++) {
        unsigned o = (unsigned)(tid + 256 * r) * 16u;
        cp16(af_sa + o, (const char*)&g_Afrag[cid][0] + o);
    }
    cp_commit();
    cp_wait0();
    __syncthreads();

    const int wid  = tid >> 5;
    const int lane = tid & 31;
    const int mt   = wid & 1;
    const int kh   = (wid >> 1) & 1;
    const int nh   = wid >> 2;
    const int lg   = lane >> 2, lt = lane & 3;

    for (int s = 0; s < TT; s++) {
        const int pb = s & 1, nb = pb ^ 1;
        const int tg = dir ? (TT - 1 - s) : s;

        // issue 8 x 16KB h-frag bulks (quads of ks) + G/mask cp.async
        if (tid == 0) {
#pragma unroll
            for (int q = 0; q < 8; q++) {
                mbar_expect_tx(MB + q * 8, 16384u);
                bulk_g2s(hf_sa + (unsigned)q * 16384u,
                         &g_hfrag[pb][dir][q * 4096], 16384u, MB + q * 8);
            }
        }
#pragma unroll
        for (int i = 0; i < 2; i++) {
            int seg = tid + 256 * i;           // 0..511
            int row = seg >> 4, part = seg & 15;
            const float* src = g_G + ((size_t)(dir * TT + s) * G4
                + (row >> 3) * HH + j0 + (row & 7)) * BB + part * 4;
            cp16(gs_sa + (unsigned)(row * 272 + part * 16), src);
        }
        if (tid < 16)
            cp16(mk_sa + tid * 16, mask + (size_t)tg * BB + tid * 4);
        cp_commit();

        // ---- GEMM: warp (mt, kh, nh): 16 ksteps, n8t = nh*4..+3 ----
        float c[4][4];
#pragma unroll
        for (int j = 0; j < 4; j++)
#pragma unroll
            for (int r = 0; r < 4; r++) c[j][r] = 0.0f;

        const unsigned a_hi_base = af_sa + (unsigned)((mt * 32) * 32 + lane) * 16u;
        const unsigned a_lo_base = a_hi_base + 32768u;

#pragma unroll 4
        for (int ki = 0; ki < 16; ki++) {
            const int ks = kh * 16 + ki;
            if ((ki & 3) == 0) mbar_wait(MB + (ks >> 2) * 8, (unsigned)(s & 1));
            u32 ah[4], al[4];
            {
                uint4 v = *(const uint4*)(smem + SB_AF +
                    ((size_t)((mt * 32 + ks) * 32 + lane)) * 16);
                ah[0] = v.x; ah[1] = v.y; ah[2] = v.z; ah[3] = v.w;
                uint4 w = *(const uint4*)(smem + SB_AF + 65536/2 +
                    ((size_t)((mt * 32 + ks) * 32 + lane)) * 16);
                al[0] = w.x; al[1] = w.y; al[2] = w.z; al[3] = w.w;
            }
#pragma unroll
            for (int j = 0; j < 4; j++) {
                const int n8t = nh * 4 + j;
                const char* bb = smem + SB_HF +
                    ((size_t)((ks * 2 + 0) * 8 + n8t) * 32 + lane) * 8;
                u64 bh = *(const u64*)bb;                     // hi regs
                u64 bl = *(const u64*)(bb + 512 * 4);         // lo: hl stride 512 u32
                u32 bh0 = (u32)bh, bh1 = (u32)(bh >> 32);
                u32 bl0 = (u32)bl, bl1 = (u32)(bl >> 32);
                mma16816(c[j], ah, bh0, bh1);
                mma16816(c[j], al, bh0, bh1);
                mma16816(c[j], ah, bl0, bl1);
            }
        }

        // partial planes: Dex[kh][row][col] (stride 66)
        {
            float* dp = Dex + kh * 2112;
            const int row0 = mt * 16 + lg;
#pragma unroll
            for (int j = 0; j < 4; j++) {
                const int col = (nh * 4 + j) * 8 + 2 * lt;
                *(float2*)&dp[row0 * 66 + col]       = make_float2(c[j][0], c[j][1]);
                *(float2*)&dp[(row0 + 8) * 66 + col] = make_float2(c[j][2], c[j][3]);
            }
        }
        cp_wait0();
        __syncthreads();

        // ---- epilogue: thread (b = tid&63, u0 = (tid>>6)*2) ----
        {
            const int b = tid & 63;
            const int u0 = (tid >> 6) * 2;
            const float m = Ms[b];
            float hn[2];
#pragma unroll
            for (int q = 0; q < 2; q++) {
                const int u = u0 + q;
                float pi = Dex[u * 66 + b]        + Dex[2112 + u * 66 + b]        + Gs[u * 68 + b];
                float pf = Dex[(8 + u) * 66 + b]  + Dex[2112 + (8 + u) * 66 + b]  + Gs[(8 + u) * 68 + b];
                float pg = Dex[(16 + u) * 66 + b] + Dex[2112 + (16 + u) * 66 + b] + Gs[(16 + u) * 68 + b];
                float po = Dex[(24 + u) * 66 + b] + Dex[2112 + (24 + u) * 66 + b] + Gs[(24 + u) * 68 + b];
                float ig = sigf(pi), fg = sigf(pf);
                float gg = tanhfast(pg), og = sigf(po);
                float c_old = cs[u * 66 + b];
                float c2 = fg * c_old + ig * gg;
                float h2 = og * tanhfast(c2);
                float c_new = c_old + m * (c2 - c_old);
                float h_old = hs[u * 66 + b];
                float h_new = h_old + m * (h2 - h_old);
                cs[u * 66 + b] = c_new;
                hs[u * 66 + b] = h_new;
                hn[q] = h_new;
            }
            *(float2*)&out[(size_t)tg * (BB * 1024) + (size_t)b * 1024
                           + dir * HH + j0 + u0] = make_float2(hn[0], hn[1]);
            // publish fragment-ordered bf16 hi/lo
            float b0h = __bfloat162float(__float2bfloat16(hn[0]));
            float b1h = __bfloat162float(__float2bfloat16(hn[1]));
            u32 hi = packbf2(hn[0], hn[1]);
            u32 lo = packbf2(hn[0] - b0h, hn[1] - b1h);
            const int ks2 = j0 >> 4;
            const int reg = (j0 & 15) >> 3;
            const int n8t = b >> 3;
            const int lane2 = (b & 7) * 4 + (u0 >> 1);
            u32* dst = &g_hfrag[nb][dir][((ks2 * 2 + 0) * 8 + n8t) * 64 + lane2 * 2 + reg];
            dst[0]   = hi;      // hl = 0
            dst[512] = lo;      // hl = 1 (stride 8*64 = 512 u32)
        }
        grid_barrier();
    }
}

// ---------------- Launch ----------------
extern "C" void kernel_launch(void* const* d_in, const int* in_sizes, int n_in,
                              void* d_out, int out_size) {
    const float* x_data = (const float*)d_in[0];
    const float* x_mask = (const float*)d_in[1];
    const float* Wih_f  = (const float*)d_in[2];
    const float* Whh_f  = (const float*)d_in[3];
    const float* bih_f  = (const float*)d_in[4];
    const float* bhh_f  = (const float*)d_in[5];
    const float* Wih_r  = (const float*)d_in[6];
    const float* Whh_r  = (const float*)d_in[7];
    const float* bih_r  = (const float*)d_in[8];
    const float* bhh_r  = (const float*)d_in[9];
    float* out = (float*)d_out;

    static bool attr_set = false;
    if (!attr_set) {
        cudaFuncSetAttribute(phase2_kernel,
                             cudaFuncAttributeMaxDynamicSharedMemorySize, SMEM2);
        attr_set = true;
    }
    dim3 g1(16, 512, 2);
    phase1_kernel<<<g1, 256>>>(x_data, Wih_f, Wih_r, bih_f, bhh_f, bih_r, bhh_r);
    prep_kernel<<<NCTA, 256>>>(Whh_f, Whh_r);
    phase2_kernel<<<NCTA, 256, SMEM2>>>(x_mask, out);
}

// round 12
// speedup vs baseline: 2.4189x; 1.4271x over previous
#include <cuda_runtime.h>
#include <cuda_bf16.h>
#include <cstdint>

typedef unsigned long long u64;
typedef unsigned u32;

#define TT 512
#define BB 64
#define DD 512
#define HH 512
#define G4 2048
#define NCTA 128

// ---------------- global scratch ----------------
__device__ float g_G[(size_t)2 * TT * G4 * BB];   // x@Wih^T + bias
__device__ u32 g_Afrag[NCTA][16384];              // Whh frags (phase2)
__device__ u32 g_hfrag[2][2][32768];              // h frags (phase2)
__device__ u32 g_Xfrag[TT][32768];                // x frags (phase1 B)
__device__ u32 g_P1A[2097152];                    // Wih frags (phase1 A) 8MB
__device__ unsigned g_bar_count;
__device__ volatile unsigned g_bar_gen;

// ---------------- helpers ----------------
__device__ __forceinline__ float sigf(float x)  { return 1.0f / (1.0f + __expf(-x)); }
__device__ __forceinline__ float tanhfast(float x) {
    return 2.0f / (1.0f + __expf(-2.0f * x)) - 1.0f;
}
__device__ __forceinline__ unsigned smem_u32(const void* p) {
    return (unsigned)__cvta_generic_to_shared(p);
}
__device__ __forceinline__ void cp16(unsigned dst, const void* src) {
    asm volatile("cp.async.cg.shared.global [%0], [%1], 16;" :: "r"(dst), "l"(src) : "memory");
}
__device__ __forceinline__ void cp_commit() { asm volatile("cp.async.commit_group;" ::: "memory"); }
__device__ __forceinline__ void cp_wait0()  { asm volatile("cp.async.wait_group 0;" ::: "memory"); }
__device__ __forceinline__ void cp_wait1()  { asm volatile("cp.async.wait_group 1;" ::: "memory"); }

__device__ __forceinline__ void mbar_init(unsigned a, unsigned c) {
    asm volatile("mbarrier.init.shared.b64 [%0], %1;" :: "r"(a), "r"(c) : "memory");
}
__device__ __forceinline__ void mbar_expect_tx(unsigned a, unsigned b) {
    asm volatile("mbarrier.arrive.expect_tx.shared.b64 _, [%0], %1;" :: "r"(a), "r"(b) : "memory");
}
__device__ __forceinline__ void bulk_g2s(unsigned dst, const void* src, unsigned bytes, unsigned mb) {
    asm volatile("cp.async.bulk.shared::cta.global.mbarrier::complete_tx::bytes [%0], [%1], %2, [%3];"
                 :: "r"(dst), "l"(src), "r"(bytes), "r"(mb) : "memory");
}
__device__ __forceinline__ void mbar_wait(unsigned a, unsigned par) {
    asm volatile(
        "{\n\t.reg .pred P;\n\t"
        "WL_%=:\n\t"
        "mbarrier.try_wait.parity.acquire.cta.shared::cta.b64 P, [%0], %1, 0x989680;\n\t"
        "@P bra.uni WD_%=;\n\t"
        "bra.uni WL_%=;\n\t"
        "WD_%=:\n\t}"
        :: "r"(a), "r"(par) : "memory");
}

__device__ __forceinline__ void mma16816(float* c, const u32* a, u32 b0, u32 b1) {
    asm volatile(
        "mma.sync.aligned.m16n8k16.row.col.f32.bf16.bf16.f32 "
        "{%0,%1,%2,%3}, {%4,%5,%6,%7}, {%8,%9}, {%0,%1,%2,%3};"
        : "+f"(c[0]), "+f"(c[1]), "+f"(c[2]), "+f"(c[3])
        : "r"(a[0]), "r"(a[1]), "r"(a[2]), "r"(a[3]), "r"(b0), "r"(b1));
}
__device__ __forceinline__ u32 packbf2(float e0, float e1) {
    __nv_bfloat162 v = __float22bfloat162_rn(make_float2(e0, e1));
    return *(u32*)&v;
}

__device__ __forceinline__ void grid_barrier() {
    __syncthreads();
    if (threadIdx.x == 0) {
        unsigned gen = g_bar_gen;
        __threadfence();
        if (atomicAdd(&g_bar_count, 1u) == NCTA - 1) {
            g_bar_count = 0; __threadfence(); g_bar_gen = gen + 1;
        } else { while (g_bar_gen == gen) { } }
        __threadfence();
    }
    __syncthreads();
}

// ---------------- xconv: x -> B-fragment images (same layout as h frags) ----
__global__ void __launch_bounds__(256) xconv_kernel(const float* __restrict__ x)
{
    int idx = blockIdx.x * 256 + threadIdx.x;    // 8,388,608
    int reg = idx & 1;
    int lane = (idx >> 1) & 31;
    int n8t = (idx >> 6) & 7;
    int ks  = (idx >> 9) & 31;
    int t   = idx >> 14;
    int g = lane >> 2, t4 = lane & 3;
    int b = n8t * 8 + g;
    int k = ks * 16 + reg * 8 + t4 * 2;
    const float* xp = x + ((size_t)t * BB + b) * DD + k;
    float x0 = xp[0], x1 = xp[1];
    float h0 = __bfloat162float(__float2bfloat16(x0));
    float h1 = __bfloat162float(__float2bfloat16(x1));
    u32* dst = g_Xfrag[t];
    dst[((ks * 2 + 0) * 8 + n8t) * 64 + lane * 2 + reg] = packbf2(x0, x1);
    dst[((ks * 2 + 1) * 8 + n8t) * 64 + lane * 2 + reg] = packbf2(x0 - h0, x1 - h1);
}

// ---------------- prep1: Wih A-fragment images ------------------------------
// store idx (per dir,mg): kc*8192 + ((hl*8+mt8)*4+ksl)*128 + lane*4 + reg
__global__ void __launch_bounds__(256) prep1_kernel(
    const float* __restrict__ Wf, const float* __restrict__ Wr)
{
    const int bg = blockIdx.x;            // dir*16+mg
    const int dir = bg >> 4, mg = bg & 15;
    const float* __restrict__ W = dir ? Wr : Wf;
    u32* dst = g_P1A + (size_t)bg * 65536;
    for (int idx = threadIdx.x; idx < 65536; idx += 256) {
        int reg = idx & 3;
        int lane = (idx >> 2) & 31;
        int ksl = (idx >> 7) & 3;
        int mt8 = (idx >> 9) & 7;
        int hl  = (idx >> 12) & 1;
        int kc  = idx >> 13;
        int g = lane >> 2, t4 = lane & 3;
        int m = mg * 128 + mt8 * 16 + g + ((reg & 1) ? 8 : 0);
        int k = kc * 64 + ksl * 16 + 2 * t4 + ((reg & 2) ? 8 : 0);
        const float* wp = W + (size_t)m * DD + k;
        float w0 = wp[0], w1 = wp[1];
        if (hl == 0) dst[idx] = packbf2(w0, w1);
        else {
            float r0 = w0 - __bfloat162float(__float2bfloat16(w0));
            float r1 = w1 - __bfloat162float(__float2bfloat16(w1));
            dst[idx] = packbf2(r0, r1);
        }
    }
}

// ---------------- phase1_mma: G = x@Wih^T + bias via mma.sync ---------------
#define P1_STAGE 65536
#define P1_BIAS  131072
#define P1_SMEM  131584

#define P1_ISSUE(c, slot) do {                                                  \
    unsigned sa = smem_u32(smem + (slot) * P1_STAGE);                           \
    const char* as = (const char*)(Abase + (size_t)(c) * 8192);                 \
    _Pragma("unroll")                                                           \
    for (int i = 0; i < 8; i++)                                                 \
        cp16(sa + (unsigned)(tid + 256 * i) * 16u, as + (size_t)(tid + 256 * i) * 16); \
    unsigned sb = sa + 32768u;                                                  \
    const char* b0 = (const char*)(B0 + (size_t)(c) * 4096);                    \
    const char* b1 = (const char*)(B1 + (size_t)(c) * 4096);                    \
    _Pragma("unroll")                                                           \
    for (int i = 0; i < 4; i++) {                                               \
        cp16(sb + (unsigned)(tid + 256 * i) * 16u, b0 + (size_t)(tid + 256 * i) * 16); \
        cp16(sb + 16384u + (unsigned)(tid + 256 * i) * 16u, b1 + (size_t)(tid + 256 * i) * 16); \
    }                                                                           \
    cp_commit();                                                                \
} while (0)

__global__ void __launch_bounds__(256) phase1_mma_kernel(
    const float* __restrict__ bif, const float* __restrict__ bhf,
    const float* __restrict__ bir, const float* __restrict__ bhr)
{
    extern __shared__ __align__(16) char smem[];
    const int tid = threadIdx.x;
    const int mg = blockIdx.x, tp = blockIdx.y, dir = blockIdx.z;
    float* bias = (float*)(smem + P1_BIAS);
    if (tid < 128) {
        int n = mg * 128 + tid;
        bias[tid] = dir ? (bir[n] + bhr[n]) : (bif[n] + bhf[n]);
    }
    const u32* Abase = g_P1A + (size_t)(dir * 16 + mg) * 65536;
    const u32* B0 = g_Xfrag[tp * 2];
    const u32* B1 = g_Xfrag[tp * 2 + 1];

    P1_ISSUE(0, 0);
    P1_ISSUE(1, 1);

    const int w = tid >> 5, lane = tid & 31;
    const int lg = lane >> 2, lt = lane & 3;
    float cf[16][4];
#pragma unroll
    for (int j = 0; j < 16; j++)
#pragma unroll
        for (int r = 0; r < 4; r++) cf[j][r] = 0.0f;

    for (int ch = 0; ch < 8; ch++) {
        if (ch == 7) cp_wait0(); else cp_wait1();
        __syncthreads();
        const char* As = smem + (ch & 1) * P1_STAGE;
        const char* Bs = As + 32768;
#pragma unroll
        for (int ksl = 0; ksl < 4; ksl++) {
            uint4 vh = *(const uint4*)(As + ((size_t)(w * 4 + ksl) * 128 + lane * 4) * 4);
            uint4 vl = *(const uint4*)(As + 16384 + ((size_t)(w * 4 + ksl) * 128 + lane * 4) * 4);
            u32 ah[4] = {vh.x, vh.y, vh.z, vh.w};
            u32 al[4] = {vl.x, vl.y, vl.z, vl.w};
#pragma unroll
            for (int j = 0; j < 16; j++) {
                const int t_loc = j >> 3, n8t = j & 7;
                const char* bb = Bs + t_loc * 16384
                    + ((size_t)((ksl * 2 + 0) * 8 + n8t) * 32 + lane) * 8;
                u64 bh = *(const u64*)bb;
                u64 bl = *(const u64*)(bb + 2048);
                mma16816(cf[j], ah, (u32)bh, (u32)(bh >> 32));
                mma16816(cf[j], al, (u32)bh, (u32)(bh >> 32));
                mma16816(cf[j], ah, (u32)bl, (u32)(bl >> 32));
            }
        }
        __syncthreads();
        if (ch + 2 < 8) P1_ISSUE(ch + 2, ch & 1);
    }

    // epilogue: add bias, store fp32 G
    const int r0 = mg * 128 + w * 16 + lg;
    const float bs0 = bias[w * 16 + lg];
    const float bs1 = bias[w * 16 + lg + 8];
#pragma unroll
    for (int j = 0; j < 16; j++) {
        int n = j * 8 + 2 * lt;
        int t_loc = n >> 6, b = n & 63;
        int t = tp * 2 + t_loc;
        int s = dir ? (TT - 1 - t) : t;
        float* gp = g_G + ((size_t)(dir * TT + s) * G4 + r0) * BB + b;
        *(float2*)gp = make_float2(cf[j][0] + bs0, cf[j][1] + bs0);
        *(float2*)(gp + 8 * BB) = make_float2(cf[j][2] + bs1, cf[j][3] + bs1);
    }
}

// ---------------- prep: Whh fragment images (unchanged, R11-passing) --------
__global__ void __launch_bounds__(256) prep_kernel(
    const float* __restrict__ Whf, const float* __restrict__ Whr)
{
    const int cid = blockIdx.x;
    const int dir = cid >> 6;
    const int j0  = (cid & 63) * 8;
    const float* __restrict__ W = dir ? Whr : Whf;
    for (int idx = threadIdx.x; idx < 16384; idx += 256) {
        int hl = idx >> 13;
        int rem = idx & 8191;
        int mt = rem >> 12;
        int ks = (rem >> 7) & 31;
        int lane = (rem >> 2) & 31;
        int reg = rem & 3;
        int g = lane >> 2, t = lane & 3;
        int m = mt * 16 + g + ((reg & 1) ? 8 : 0);
        int k = ks * 16 + 2 * t + ((reg & 2) ? 8 : 0);
        int gate = m >> 3, u = m & 7;
        const float* wr = W + (size_t)(gate * HH + j0 + u) * HH + k;
        float w0 = wr[0], w1 = wr[1];
        if (hl == 0) {
            g_Afrag[cid][idx] = packbf2(w0, w1);
        } else {
            float r0 = w0 - __bfloat162float(__float2bfloat16(w0));
            float r1 = w1 - __bfloat162float(__float2bfloat16(w1));
            g_Afrag[cid][idx] = packbf2(r0, r1);
        }
    }
    {
        int i = blockIdx.x * 256 + threadIdx.x;
        u64* Z = (u64*)&g_hfrag[0][0][0];
        if (i < 32768) Z[i] = 0ull;
    }
}

// ---------------- Phase 2 (unchanged, R11-passing) --------------------------
#define SB_AF  0
#define SB_HF  65536
#define SB_GS  196608
#define SB_DEX 205312
#define SB_CS  222208
#define SB_HS  224320
#define SB_MK  226432
#define SB_MB  226688
#define SMEM2  226816

__global__ void __launch_bounds__(256) phase2_kernel(
    const float* __restrict__ mask, float* __restrict__ out)
{
    extern __shared__ __align__(16) char smem[];
    float* Gs  = (float*)(smem + SB_GS);
    float* Dex = (float*)(smem + SB_DEX);
    float* cs  = (float*)(smem + SB_CS);
    float* hs  = (float*)(smem + SB_HS);
    float* Ms  = (float*)(smem + SB_MK);
    const unsigned af_sa = smem_u32(smem + SB_AF);
    const unsigned hf_sa = smem_u32(smem + SB_HF);
    const unsigned gs_sa = smem_u32(smem + SB_GS);
    const unsigned mk_sa = smem_u32(smem + SB_MK);
    const unsigned MB    = smem_u32(smem + SB_MB);

    const int tid = threadIdx.x;
    const int cid = blockIdx.x;
    const int dir = cid >> 6;
    const int j0  = (cid & 63) * 8;

    if (tid < 8) mbar_init(MB + tid * 8, 1);
    for (int i = tid; i < 528; i += 256) { cs[i] = 0.0f; hs[i] = 0.0f; }
#pragma unroll
    for (int r = 0; r < 16; r++) {
        unsigned o = (unsigned)(tid + 256 * r) * 16u;
        cp16(af_sa + o, (const char*)&g_Afrag[cid][0] + o);
    }
    cp_commit();
    cp_wait0();
    __syncthreads();

    const int wid  = tid >> 5;
    const int lane = tid & 31;
    const int mt   = wid & 1;
    const int kh   = (wid >> 1) & 1;
    const int nh   = wid >> 2;
    const int lg   = lane >> 2, lt = lane & 3;

    for (int s = 0; s < TT; s++) {
        const int pb = s & 1, nb = pb ^ 1;
        const int tg = dir ? (TT - 1 - s) : s;

        if (tid == 0) {
#pragma unroll
            for (int q = 0; q < 8; q++) {
                mbar_expect_tx(MB + q * 8, 16384u);
                bulk_g2s(hf_sa + (unsigned)q * 16384u,
                         &g_hfrag[pb][dir][q * 4096], 16384u, MB + q * 8);
            }
        }
#pragma unroll
        for (int i = 0; i < 2; i++) {
            int seg = tid + 256 * i;
            int row = seg >> 4, part = seg & 15;
            const float* src = g_G + ((size_t)(dir * TT + s) * G4
                + (row >> 3) * HH + j0 + (row & 7)) * BB + part * 4;
            cp16(gs_sa + (unsigned)(row * 272 + part * 16), src);
        }
        if (tid < 16)
            cp16(mk_sa + tid * 16, mask + (size_t)tg * BB + tid * 4);
        cp_commit();

        float c[4][4];
#pragma unroll
        for (int j = 0; j < 4; j++)
#pragma unroll
            for (int r = 0; r < 4; r++) c[j][r] = 0.0f;

#pragma unroll 4
        for (int ki = 0; ki < 16; ki++) {
            const int ks = kh * 16 + ki;
            if ((ki & 3) == 0) mbar_wait(MB + (ks >> 2) * 8, (unsigned)(s & 1));
            u32 ah[4], al[4];
            {
                uint4 v = *(const uint4*)(smem + SB_AF +
                    ((size_t)((mt * 32 + ks) * 32 + lane)) * 16);
                ah[0] = v.x; ah[1] = v.y; ah[2] = v.z; ah[3] = v.w;
                uint4 w2 = *(const uint4*)(smem + SB_AF + 65536 / 2 +
                    ((size_t)((mt * 32 + ks) * 32 + lane)) * 16);
                al[0] = w2.x; al[1] = w2.y; al[2] = w2.z; al[3] = w2.w;
            }
#pragma unroll
            for (int j = 0; j < 4; j++) {
                const int n8t = nh * 4 + j;
                const char* bb = smem + SB_HF +
                    ((size_t)((ks * 2 + 0) * 8 + n8t) * 32 + lane) * 8;
                u64 bh = *(const u64*)bb;
                u64 bl = *(const u64*)(bb + 512 * 4);
                u32 bh0 = (u32)bh, bh1 = (u32)(bh >> 32);
                u32 bl0 = (u32)bl, bl1 = (u32)(bl >> 32);
                mma16816(c[j], ah, bh0, bh1);
                mma16816(c[j], al, bh0, bh1);
                mma16816(c[j], ah, bl0, bl1);
            }
        }

        {
            float* dp = Dex + kh * 2112;
            const int row0 = mt * 16 + lg;
#pragma unroll
            for (int j = 0; j < 4; j++) {
                const int col = (nh * 4 + j) * 8 + 2 * lt;
                *(float2*)&dp[row0 * 66 + col]       = make_float2(c[j][0], c[j][1]);
                *(float2*)&dp[(row0 + 8) * 66 + col] = make_float2(c[j][2], c[j][3]);
            }
        }
        cp_wait0();
        __syncthreads();

        {
            const int b = tid & 63;
            const int u0 = (tid >> 6) * 2;
            const float m = Ms[b];
            float hn[2];
#pragma unroll
            for (int q = 0; q < 2; q++) {
                const int u = u0 + q;
                float pi = Dex[u * 66 + b]        + Dex[2112 + u * 66 + b]        + Gs[u * 68 + b];
                float pf = Dex[(8 + u) * 66 + b]  + Dex[2112 + (8 + u) * 66 + b]  + Gs[(8 + u) * 68 + b];
                float pg = Dex[(16 + u) * 66 + b] + Dex[2112 + (16 + u) * 66 + b] + Gs[(16 + u) * 68 + b];
                float po = Dex[(24 + u) * 66 + b] + Dex[2112 + (24 + u) * 66 + b] + Gs[(24 + u) * 68 + b];
                float ig = sigf(pi), fg = sigf(pf);
                float gg = tanhfast(pg), og = sigf(po);
                float c_old = cs[u * 66 + b];
                float c2 = fg * c_old + ig * gg;
                float h2 = og * tanhfast(c2);
                float c_new = c_old + m * (c2 - c_old);
                float h_old = hs[u * 66 + b];
                float h_new = h_old + m * (h2 - h_old);
                cs[u * 66 + b] = c_new;
                hs[u * 66 + b] = h_new;
                hn[q] = h_new;
            }
            *(float2*)&out[(size_t)tg * (BB * 1024) + (size_t)b * 1024
                           + dir * HH + j0 + u0] = make_float2(hn[0], hn[1]);
            float b0h = __bfloat162float(__float2bfloat16(hn[0]));
            float b1h = __bfloat162float(__float2bfloat16(hn[1]));
            u32 hi = packbf2(hn[0], hn[1]);
            u32 lo = packbf2(hn[0] - b0h, hn[1] - b1h);
            const int ks2 = j0 >> 4;
            const int reg = (j0 & 15) >> 3;
            const int n8t = b >> 3;
            const int lane2 = (b & 7) * 4 + (u0 >> 1);
            u32* dst = &g_hfrag[nb][dir][((ks2 * 2 + 0) * 8 + n8t) * 64 + lane2 * 2 + reg];
            dst[0]   = hi;
            dst[512] = lo;
        }
        grid_barrier();
    }
}

// ---------------- Launch ----------------
extern "C" void kernel_launch(void* const* d_in, const int* in_sizes, int n_in,
                              void* d_out, int out_size) {
    const float* x_data = (const float*)d_in[0];
    const float* x_mask = (const float*)d_in[1];
    const float* Whh_f  = (const float*)d_in[3];
    const float* bih_f  = (const float*)d_in[4];
    const float* bhh_f  = (const float*)d_in[5];
    const float* Wih_f  = (const float*)d_in[2];
    const float* Wih_r  = (const float*)d_in[6];
    const float* Whh_r  = (const float*)d_in[7];
    const float* bih_r  = (const float*)d_in[8];
    const float* bhh_r  = (const float*)d_in[9];
    float* out = (float*)d_out;

    static bool attr_set = false;
    if (!attr_set) {
        cudaFuncSetAttribute(phase2_kernel,
                             cudaFuncAttributeMaxDynamicSharedMemorySize, SMEM2);
        cudaFuncSetAttribute(phase1_mma_kernel,
                             cudaFuncAttributeMaxDynamicSharedMemorySize, P1_SMEM);
        attr_set = true;
    }
    xconv_kernel<<<32768, 256>>>(x_data);
    prep1_kernel<<<32, 256>>>(Wih_f, Wih_r);
    prep_kernel<<<NCTA, 256>>>(Whh_f, Whh_r);
    phase1_mma_kernel<<<dim3(16, 256, 2), 256, P1_SMEM>>>(bih_f, bhh_f, bih_r, bhh_r);
    phase2_kernel<<<NCTA, 256, SMEM2>>>(x_mask, out);
}

// round 13
// speedup vs baseline: 2.6035x; 1.0763x over previous
#include <cuda_runtime.h>
#include <cuda_bf16.h>
#include <cstdint>

typedef unsigned long long u64;
typedef unsigned u32;

#define TT 512
#define BB 64
#define DD 512
#define HH 512
#define G4 2048
#define NCTA 128

// ---------------- global scratch ----------------
__device__ float g_G[(size_t)2 * TT * G4 * BB];   // x@Wih^T + bias
__device__ u32 g_Afrag[NCTA][16384];              // Whh frags (phase2)
__device__ u32 g_hfrag[2][2][32768];              // h frags (phase2)
__device__ u32 g_Xfrag[TT][32768];                // x frags (phase1 B)
__device__ u32 g_P1A[2097152];                    // Wih frags (phase1 A) 8MB
__device__ unsigned g_rdy[2][8];                  // per (dir, chunk) publish counters

// ---------------- helpers ----------------
__device__ __forceinline__ float sigf(float x)  { return 1.0f / (1.0f + __expf(-x)); }
__device__ __forceinline__ float tanhfast(float x) {
    return 2.0f / (1.0f + __expf(-2.0f * x)) - 1.0f;
}
__device__ __forceinline__ unsigned smem_u32(const void* p) {
    return (unsigned)__cvta_generic_to_shared(p);
}
__device__ __forceinline__ void cp16(unsigned dst, const void* src) {
    asm volatile("cp.async.cg.shared.global [%0], [%1], 16;" :: "r"(dst), "l"(src) : "memory");
}
__device__ __forceinline__ void cp_commit() { asm volatile("cp.async.commit_group;" ::: "memory"); }
__device__ __forceinline__ void cp_wait0()  { asm volatile("cp.async.wait_group 0;" ::: "memory"); }
__device__ __forceinline__ void cp_wait1()  { asm volatile("cp.async.wait_group 1;" ::: "memory"); }

__device__ __forceinline__ void mbar_init(unsigned a, unsigned c) {
    asm volatile("mbarrier.init.shared.b64 [%0], %1;" :: "r"(a), "r"(c) : "memory");
}
__device__ __forceinline__ void mbar_expect_tx(unsigned a, unsigned b) {
    asm volatile("mbarrier.arrive.expect_tx.shared.b64 _, [%0], %1;" :: "r"(a), "r"(b) : "memory");
}
__device__ __forceinline__ void bulk_g2s(unsigned dst, const void* src, unsigned bytes, unsigned mb) {
    asm volatile("cp.async.bulk.shared::cta.global.mbarrier::complete_tx::bytes [%0], [%1], %2, [%3];"
                 :: "r"(dst), "l"(src), "r"(bytes), "r"(mb) : "memory");
}
__device__ __forceinline__ void mbar_wait(unsigned a, unsigned par) {
    asm volatile(
        "{\n\t.reg .pred P;\n\t"
        "WL_%=:\n\t"
        "mbarrier.try_wait.parity.acquire.cta.shared::cta.b64 P, [%0], %1, 0x989680;\n\t"
        "@P bra.uni WD_%=;\n\t"
        "bra.uni WL_%=;\n\t"
        "WD_%=:\n\t}"
        :: "r"(a), "r"(par) : "memory");
}

__device__ __forceinline__ void mma16816(float* c, const u32* a, u32 b0, u32 b1) {
    asm volatile(
        "mma.sync.aligned.m16n8k16.row.col.f32.bf16.bf16.f32 "
        "{%0,%1,%2,%3}, {%4,%5,%6,%7}, {%8,%9}, {%0,%1,%2,%3};"
        : "+f"(c[0]), "+f"(c[1]), "+f"(c[2]), "+f"(c[3])
        : "r"(a[0]), "r"(a[1]), "r"(a[2]), "r"(a[3]), "r"(b0), "r"(b1));
}
__device__ __forceinline__ u32 packbf2(float e0, float e1) {
    __nv_bfloat162 v = __float22bfloat162_rn(make_float2(e0, e1));
    return *(u32*)&v;
}

// ---------------- xconv: x -> B-fragment images (same layout as h frags) ----
__global__ void __launch_bounds__(256) xconv_kernel(const float* __restrict__ x)
{
    int idx = blockIdx.x * 256 + threadIdx.x;    // 8,388,608
    int reg = idx & 1;
    int lane = (idx >> 1) & 31;
    int n8t = (idx >> 6) & 7;
    int ks  = (idx >> 9) & 31;
    int t   = idx >> 14;
    int g = lane >> 2, t4 = lane & 3;
    int b = n8t * 8 + g;
    int k = ks * 16 + reg * 8 + t4 * 2;
    const float* xp = x + ((size_t)t * BB + b) * DD + k;
    float x0 = xp[0], x1 = xp[1];
    float h0 = __bfloat162float(__float2bfloat16(x0));
    float h1 = __bfloat162float(__float2bfloat16(x1));
    u32* dst = g_Xfrag[t];
    dst[((ks * 2 + 0) * 8 + n8t) * 64 + lane * 2 + reg] = packbf2(x0, x1);
    dst[((ks * 2 + 1) * 8 + n8t) * 64 + lane * 2 + reg] = packbf2(x0 - h0, x1 - h1);
}

// ---------------- prep1: Wih A-fragment images ------------------------------
__global__ void __launch_bounds__(256) prep1_kernel(
    const float* __restrict__ Wf, const float* __restrict__ Wr)
{
    const int bg = blockIdx.x;            // dir*16+mg
    const int dir = bg >> 4, mg = bg & 15;
    const float* __restrict__ W = dir ? Wr : Wf;
    u32* dst = g_P1A + (size_t)bg * 65536;
    for (int idx = threadIdx.x; idx < 65536; idx += 256) {
        int reg = idx & 3;
        int lane = (idx >> 2) & 31;
        int ksl = (idx >> 7) & 3;
        int mt8 = (idx >> 9) & 7;
        int hl  = (idx >> 12) & 1;
        int kc  = idx >> 13;
        int g = lane >> 2, t4 = lane & 3;
        int m = mg * 128 + mt8 * 16 + g + ((reg & 1) ? 8 : 0);
        int k = kc * 64 + ksl * 16 + 2 * t4 + ((reg & 2) ? 8 : 0);
        const float* wp = W + (size_t)m * DD + k;
        float w0 = wp[0], w1 = wp[1];
        if (hl == 0) dst[idx] = packbf2(w0, w1);
        else {
            float r0 = w0 - __bfloat162float(__float2bfloat16(w0));
            float r1 = w1 - __bfloat162float(__float2bfloat16(w1));
            dst[idx] = packbf2(r0, r1);
        }
    }
}

// ---------------- phase1_mma: G = x@Wih^T + bias via mma.sync ---------------
#define P1_STAGE 65536
#define P1_BIAS  131072
#define P1_SMEM  131584

#define P1_ISSUE(c, slot) do {                                                  \
    unsigned sa = smem_u32(smem + (slot) * P1_STAGE);                           \
    const char* as = (const char*)(Abase + (size_t)(c) * 8192);                 \
    _Pragma("unroll")                                                           \
    for (int i = 0; i < 8; i++)                                                 \
        cp16(sa + (unsigned)(tid + 256 * i) * 16u, as + (size_t)(tid + 256 * i) * 16); \
    unsigned sb = sa + 32768u;                                                  \
    const char* b0 = (const char*)(B0 + (size_t)(c) * 4096);                    \
    const char* b1 = (const char*)(B1 + (size_t)(c) * 4096);                    \
    _Pragma("unroll")                                                           \
    for (int i = 0; i < 4; i++) {                                               \
        cp16(sb + (unsigned)(tid + 256 * i) * 16u, b0 + (size_t)(tid + 256 * i) * 16); \
        cp16(sb + 16384u + (unsigned)(tid + 256 * i) * 16u, b1 + (size_t)(tid + 256 * i) * 16); \
    }                                                                           \
    cp_commit();                                                                \
} while (0)

__global__ void __launch_bounds__(256) phase1_mma_kernel(
    const float* __restrict__ bif, const float* __restrict__ bhf,
    const float* __restrict__ bir, const float* __restrict__ bhr)
{
    extern __shared__ __align__(16) char smem[];
    const int tid = threadIdx.x;
    const int mg = blockIdx.x, tp = blockIdx.y, dir = blockIdx.z;
    float* bias = (float*)(smem + P1_BIAS);
    if (tid < 128) {
        int n = mg * 128 + tid;
        bias[tid] = dir ? (bir[n] + bhr[n]) : (bif[n] + bhf[n]);
    }
    const u32* Abase = g_P1A + (size_t)(dir * 16 + mg) * 65536;
    const u32* B0 = g_Xfrag[tp * 2];
    const u32* B1 = g_Xfrag[tp * 2 + 1];

    P1_ISSUE(0, 0);
    P1_ISSUE(1, 1);

    const int w = tid >> 5, lane = tid & 31;
    const int lg = lane >> 2, lt = lane & 3;
    float cf[16][4];
#pragma unroll
    for (int j = 0; j < 16; j++)
#pragma unroll
        for (int r = 0; r < 4; r++) cf[j][r] = 0.0f;

    for (int ch = 0; ch < 8; ch++) {
        if (ch == 7) cp_wait0(); else cp_wait1();
        __syncthreads();
        const char* As = smem + (ch & 1) * P1_STAGE;
        const char* Bs = As + 32768;
#pragma unroll
        for (int ksl = 0; ksl < 4; ksl++) {
            uint4 vh = *(const uint4*)(As + ((size_t)(w * 4 + ksl) * 128 + lane * 4) * 4);
            uint4 vl = *(const uint4*)(As + 16384 + ((size_t)(w * 4 + ksl) * 128 + lane * 4) * 4);
            u32 ah[4] = {vh.x, vh.y, vh.z, vh.w};
            u32 al[4] = {vl.x, vl.y, vl.z, vl.w};
#pragma unroll
            for (int j = 0; j < 16; j++) {
                const int t_loc = j >> 3, n8t = j & 7;
                const char* bb = Bs + t_loc * 16384
                    + ((size_t)((ksl * 2 + 0) * 8 + n8t) * 32 + lane) * 8;
                u64 bh = *(const u64*)bb;
                u64 bl = *(const u64*)(bb + 2048);
                mma16816(cf[j], ah, (u32)bh, (u32)(bh >> 32));
                mma16816(cf[j], al, (u32)bh, (u32)(bh >> 32));
                mma16816(cf[j], ah, (u32)bl, (u32)(bl >> 32));
            }
        }
        __syncthreads();
        if (ch + 2 < 8) P1_ISSUE(ch + 2, ch & 1);
    }

    const int r0 = mg * 128 + w * 16 + lg;
    const float bs0 = bias[w * 16 + lg];
    const float bs1 = bias[w * 16 + lg + 8];
#pragma unroll
    for (int j = 0; j < 16; j++) {
        int n = j * 8 + 2 * lt;
        int t_loc = n >> 6, b = n & 63;
        int t = tp * 2 + t_loc;
        int s = dir ? (TT - 1 - t) : t;
        float* gp = g_G + ((size_t)(dir * TT + s) * G4 + r0) * BB + b;
        *(float2*)gp = make_float2(cf[j][0] + bs0, cf[j][1] + bs0);
        *(float2*)(gp + 8 * BB) = make_float2(cf[j][2] + bs1, cf[j][3] + bs1);
    }
}

// ---------------- prep: Whh fragment images + resets ------------------------
__global__ void __launch_bounds__(256) prep_kernel(
    const float* __restrict__ Whf, const float* __restrict__ Whr)
{
    const int cid = blockIdx.x;
    const int dir = cid >> 6;
    const int j0  = (cid & 63) * 8;
    const float* __restrict__ W = dir ? Whr : Whf;
    for (int idx = threadIdx.x; idx < 16384; idx += 256) {
        int hl = idx >> 13;
        int rem = idx & 8191;
        int mt = rem >> 12;
        int ks = (rem >> 7) & 31;
        int lane = (rem >> 2) & 31;
        int reg = rem & 3;
        int g = lane >> 2, t = lane & 3;
        int m = mt * 16 + g + ((reg & 1) ? 8 : 0);
        int k = ks * 16 + 2 * t + ((reg & 2) ? 8 : 0);
        int gate = m >> 3, u = m & 7;
        const float* wr = W + (size_t)(gate * HH + j0 + u) * HH + k;
        float w0 = wr[0], w1 = wr[1];
        if (hl == 0) {
            g_Afrag[cid][idx] = packbf2(w0, w1);
        } else {
            float r0 = w0 - __bfloat162float(__float2bfloat16(w0));
            float r1 = w1 - __bfloat162float(__float2bfloat16(w1));
            g_Afrag[cid][idx] = packbf2(r0, r1);
        }
    }
    {
        int i = blockIdx.x * 256 + threadIdx.x;
        u64* Z = (u64*)&g_hfrag[0][0][0];
        if (i < 32768) Z[i] = 0ull;
    }
    if (cid == 0 && threadIdx.x < 16)
        ((unsigned*)g_rdy)[threadIdx.x] = 0;
}

// ---------------- Phase 2: dataflow-synced persistent mma recurrence --------
#define SB_AF  0
#define SB_HF  65536
#define SB_GS  196608
#define SB_DEX 205312
#define SB_CS  222208
#define SB_HS  224320
#define SB_MK  226432
#define SB_MB  226688
#define SMEM2  226816

__global__ void __launch_bounds__(256) phase2_kernel(
    const float* __restrict__ mask, float* __restrict__ out)
{
    extern __shared__ __align__(16) char smem[];
    float* Gs  = (float*)(smem + SB_GS);
    float* Dex = (float*)(smem + SB_DEX);
    float* cs  = (float*)(smem + SB_CS);
    float* hs  = (float*)(smem + SB_HS);
    float* Ms  = (float*)(smem + SB_MK);
    const unsigned af_sa = smem_u32(smem + SB_AF);
    const unsigned hf_sa = smem_u32(smem + SB_HF);
    const unsigned gs_sa = smem_u32(smem + SB_GS);
    const unsigned mk_sa = smem_u32(smem + SB_MK);
    const unsigned MB    = smem_u32(smem + SB_MB);

    const int tid = threadIdx.x;
    const int cid = blockIdx.x;
    const int dir = cid >> 6;
    const int j0  = (cid & 63) * 8;
    const int mychunk = (cid & 63) >> 3;

    if (tid < 8) mbar_init(MB + tid * 8, 1);
    for (int i = tid; i < 528; i += 256) { cs[i] = 0.0f; hs[i] = 0.0f; }
#pragma unroll
    for (int r = 0; r < 16; r++) {
        unsigned o = (unsigned)(tid + 256 * r) * 16u;
        cp16(af_sa + o, (const char*)&g_Afrag[cid][0] + o);
    }
    cp_commit();
    cp_wait0();
    __syncthreads();

    // prologue: issue step-0 bulks (h buffer 0 zeroed by prep)
    if (tid == 0) {
#pragma unroll
        for (int c = 0; c < 8; c++) {
            mbar_expect_tx(MB + c * 8, 16384u);
            bulk_g2s(hf_sa + (unsigned)c * 16384u,
                     &g_hfrag[0][dir][c * 4096], 16384u, MB + c * 8);
        }
    }

    const int wid  = tid >> 5;
    const int lane = tid & 31;
    const int mt   = wid & 1;
    const int kh   = (wid >> 1) & 1;
    const int nh   = wid >> 2;
    const int lg   = lane >> 2, lt = lane & 3;

    for (int s = 0; s < TT; s++) {
        const int nb = (s & 1) ^ 1;
        const int tg = dir ? (TT - 1 - s) : s;

        // G + mask cp.async for this step (overlaps MMA)
#pragma unroll
        for (int i = 0; i < 2; i++) {
            int seg = tid + 256 * i;
            int row = seg >> 4, part = seg & 15;
            const float* src = g_G + ((size_t)(dir * TT + s) * G4
                + (row >> 3) * HH + j0 + (row & 7)) * BB + part * 4;
            cp16(gs_sa + (unsigned)(row * 272 + part * 16), src);
        }
        if (tid < 16)
            cp16(mk_sa + tid * 16, mask + (size_t)tg * BB + tid * 4);
        cp_commit();

        // ---- GEMM ----
        float c[4][4];
#pragma unroll
        for (int j = 0; j < 4; j++)
#pragma unroll
            for (int r = 0; r < 4; r++) c[j][r] = 0.0f;

#pragma unroll 4
        for (int ki = 0; ki < 16; ki++) {
            const int ks = kh * 16 + ki;
            if ((ki & 3) == 0) mbar_wait(MB + (ks >> 2) * 8, (unsigned)(s & 1));
            u32 ah[4], al[4];
            {
                uint4 v = *(const uint4*)(smem + SB_AF +
                    ((size_t)((mt * 32 + ks) * 32 + lane)) * 16);
                ah[0] = v.x; ah[1] = v.y; ah[2] = v.z; ah[3] = v.w;
                uint4 w2 = *(const uint4*)(smem + SB_AF + 65536 / 2 +
                    ((size_t)((mt * 32 + ks) * 32 + lane)) * 16);
                al[0] = w2.x; al[1] = w2.y; al[2] = w2.z; al[3] = w2.w;
            }
#pragma unroll
            for (int j = 0; j < 4; j++) {
                const int n8t = nh * 4 + j;
                const char* bb = smem + SB_HF +
                    ((size_t)((ks * 2 + 0) * 8 + n8t) * 32 + lane) * 8;
                u64 bh = *(const u64*)bb;
                u64 bl = *(const u64*)(bb + 512 * 4);
                u32 bh0 = (u32)bh, bh1 = (u32)(bh >> 32);
                u32 bl0 = (u32)bl, bl1 = (u32)(bl >> 32);
                mma16816(c[j], ah, bh0, bh1);
                mma16816(c[j], al, bh0, bh1);
                mma16816(c[j], ah, bl0, bl1);
            }
        }

        {
            float* dp = Dex + kh * 2112;
            const int row0 = mt * 16 + lg;
#pragma unroll
            for (int j = 0; j < 4; j++) {
                const int col = (nh * 4 + j) * 8 + 2 * lt;
                *(float2*)&dp[row0 * 66 + col]       = make_float2(c[j][0], c[j][1]);
                *(float2*)&dp[(row0 + 8) * 66 + col] = make_float2(c[j][2], c[j][3]);
            }
        }
        cp_wait0();
        __syncthreads();

        // ---- epilogue: publish h first, then signal, then out store ----
        float hn[2];
        const int b = tid & 63;
        const int u0 = (tid >> 6) * 2;
        {
            const float m = Ms[b];
#pragma unroll
            for (int q = 0; q < 2; q++) {
                const int u = u0 + q;
                float pi = Dex[u * 66 + b]        + Dex[2112 + u * 66 + b]        + Gs[u * 68 + b];
                float pf = Dex[(8 + u) * 66 + b]  + Dex[2112 + (8 + u) * 66 + b]  + Gs[(8 + u) * 68 + b];
                float pg = Dex[(16 + u) * 66 + b] + Dex[2112 + (16 + u) * 66 + b] + Gs[(16 + u) * 68 + b];
                float po = Dex[(24 + u) * 66 + b] + Dex[2112 + (24 + u) * 66 + b] + Gs[(24 + u) * 68 + b];
                float ig = sigf(pi), fg = sigf(pf);
                float gg = tanhfast(pg), og = sigf(po);
                float c_old = cs[u * 66 + b];
                float c2 = fg * c_old + ig * gg;
                float h2 = og * tanhfast(c2);
                float c_new = c_old + m * (c2 - c_old);
                float h_old = hs[u * 66 + b];
                float h_new = h_old + m * (h2 - h_old);
                cs[u * 66 + b] = c_new;
                hs[u * 66 + b] = h_new;
                hn[q] = h_new;
            }
            float b0h = __bfloat162float(__float2bfloat16(hn[0]));
            float b1h = __bfloat162float(__float2bfloat16(hn[1]));
            u32 hi = packbf2(hn[0], hn[1]);
            u32 lo = packbf2(hn[0] - b0h, hn[1] - b1h);
            const int ks2 = j0 >> 4;
            const int reg = (j0 & 15) >> 3;
            const int n8t = b >> 3;
            const int lane2 = (b & 7) * 4 + (u0 >> 1);
            u32* dst = &g_hfrag[nb][dir][((ks2 * 2 + 0) * 8 + n8t) * 64 + lane2 * 2 + reg];
            dst[0]   = hi;
            dst[512] = lo;
        }
        __threadfence();
        __syncthreads();
        if (tid == 0) atomicAdd(&g_rdy[dir][mychunk], 1u);

        // loader for step s+1: dataflow spin per chunk, then bulk
        if (s + 1 < TT && tid == 0) {
            const unsigned target = 8u * (unsigned)(s + 1);
#pragma unroll 1
            for (int c2 = 0; c2 < 8; c2++) {
                while (*(volatile unsigned*)&g_rdy[dir][c2] < target) { }
                mbar_expect_tx(MB + c2 * 8, 16384u);
                bulk_g2s(hf_sa + (unsigned)c2 * 16384u,
                         &g_hfrag[nb][dir][c2 * 4096], 16384u, MB + c2 * 8);
            }
        }

        // output store
        *(float2*)&out[(size_t)tg * (BB * 1024) + (size_t)b * 1024
                       + dir * HH + j0 + u0] = make_float2(hn[0], hn[1]);
    }
}

// ---------------- Launch ----------------
extern "C" void kernel_launch(void* const* d_in, const int* in_sizes, int n_in,
                              void* d_out, int out_size) {
    const float* x_data = (const float*)d_in[0];
    const float* x_mask = (const float*)d_in[1];
    const float* Wih_f  = (const float*)d_in[2];
    const float* Whh_f  = (const float*)d_in[3];
    const float* bih_f  = (const float*)d_in[4];
    const float* bhh_f  = (const float*)d_in[5];
    const float* Wih_r  = (const float*)d_in[6];
    const float* Whh_r  = (const float*)d_in[7];
    const float* bih_r  = (const float*)d_in[8];
    const float* bhh_r  = (const float*)d_in[9];
    float* out = (float*)d_out;

    static bool attr_set = false;
    if (!attr_set) {
        cudaFuncSetAttribute(phase2_kernel,
                             cudaFuncAttributeMaxDynamicSharedMemorySize, SMEM2);
        cudaFuncSetAttribute(phase1_mma_kernel,
                             cudaFuncAttributeMaxDynamicSharedMemorySize, P1_SMEM);
        attr_set = true;
    }
    xconv_kernel<<<32768, 256>>>(x_data);
    prep1_kernel<<<32, 256>>>(Wih_f, Wih_r);
    prep_kernel<<<NCTA, 256>>>(Whh_f, Whh_r);
    phase1_mma_kernel<<<dim3(16, 256, 2), 256, P1_SMEM>>>(bih_f, bhh_f, bih_r, bhh_r);
    phase2_kernel<<<NCTA, 256, SMEM2>>>(x_mask, out);
}

// round 14
// speedup vs baseline: 2.7775x; 1.0669x over previous
#include <cuda_runtime.h>
#include <cuda_bf16.h>
#include <cstdint>

typedef unsigned long long u64;
typedef unsigned u32;

#define TT 512
#define BB 64
#define DD 512
#define HH 512
#define G4 2048
#define NCTA 128

// ---------------- global scratch ----------------
__device__ float g_G[(size_t)2 * TT * G4 * BB];   // x@Wih^T + bias
__device__ u32 g_Afrag[NCTA][16384];              // Whh frags (phase2)
__device__ u32 g_hfrag[2][2][32768];              // h frags (phase2)
__device__ u32 g_Xfrag[TT][32768];                // x frags (phase1 B)
__device__ u32 g_P1A[2097152];                    // Wih frags (phase1 A) 8MB
__device__ unsigned g_rdy[2][8];                  // per (dir, chunk) publish counters

// ---------------- helpers ----------------
__device__ __forceinline__ float sigf(float x)  { return 1.0f / (1.0f + __expf(-x)); }
__device__ __forceinline__ float tanhfast(float x) {
    return 2.0f / (1.0f + __expf(-2.0f * x)) - 1.0f;
}
__device__ __forceinline__ unsigned smem_u32(const void* p) {
    return (unsigned)__cvta_generic_to_shared(p);
}
__device__ __forceinline__ void cp16(unsigned dst, const void* src) {
    asm volatile("cp.async.cg.shared.global [%0], [%1], 16;" :: "r"(dst), "l"(src) : "memory");
}
__device__ __forceinline__ void cp_commit() { asm volatile("cp.async.commit_group;" ::: "memory"); }
__device__ __forceinline__ void cp_wait0()  { asm volatile("cp.async.wait_group 0;" ::: "memory"); }
__device__ __forceinline__ void cp_wait1()  { asm volatile("cp.async.wait_group 1;" ::: "memory"); }

__device__ __forceinline__ void mbar_init(unsigned a, unsigned c) {
    asm volatile("mbarrier.init.shared.b64 [%0], %1;" :: "r"(a), "r"(c) : "memory");
}
__device__ __forceinline__ void mbar_expect_tx(unsigned a, unsigned b) {
    asm volatile("mbarrier.arrive.expect_tx.shared.b64 _, [%0], %1;" :: "r"(a), "r"(b) : "memory");
}
__device__ __forceinline__ void bulk_g2s(unsigned dst, const void* src, unsigned bytes, unsigned mb) {
    asm volatile("cp.async.bulk.shared::cta.global.mbarrier::complete_tx::bytes [%0], [%1], %2, [%3];"
                 :: "r"(dst), "l"(src), "r"(bytes), "r"(mb) : "memory");
}
__device__ __forceinline__ void mbar_wait(unsigned a, unsigned par) {
    asm volatile(
        "{\n\t.reg .pred P;\n\t"
        "WL_%=:\n\t"
        "mbarrier.try_wait.parity.acquire.cta.shared::cta.b64 P, [%0], %1, 0x989680;\n\t"
        "@P bra.uni WD_%=;\n\t"
        "bra.uni WL_%=;\n\t"
        "WD_%=:\n\t}"
        :: "r"(a), "r"(par) : "memory");
}

__device__ __forceinline__ void mma16816(float* c, const u32* a, u32 b0, u32 b1) {
    asm volatile(
        "mma.sync.aligned.m16n8k16.row.col.f32.bf16.bf16.f32 "
        "{%0,%1,%2,%3}, {%4,%5,%6,%7}, {%8,%9}, {%0,%1,%2,%3};"
        : "+f"(c[0]), "+f"(c[1]), "+f"(c[2]), "+f"(c[3])
        : "r"(a[0]), "r"(a[1]), "r"(a[2]), "r"(a[3]), "r"(b0), "r"(b1));
}
__device__ __forceinline__ u32 packbf2(float e0, float e1) {
    __nv_bfloat162 v = __float22bfloat162_rn(make_float2(e0, e1));
    return *(u32*)&v;
}

// ---------------- xconv: x -> B-fragment images (same layout as h frags) ----
__global__ void __launch_bounds__(256) xconv_kernel(const float* __restrict__ x)
{
    int idx = blockIdx.x * 256 + threadIdx.x;    // 8,388,608
    int reg = idx & 1;
    int lane = (idx >> 1) & 31;
    int n8t = (idx >> 6) & 7;
    int ks  = (idx >> 9) & 31;
    int t   = idx >> 14;
    int g = lane >> 2, t4 = lane & 3;
    int b = n8t * 8 + g;
    int k = ks * 16 + reg * 8 + t4 * 2;
    const float* xp = x + ((size_t)t * BB + b) * DD + k;
    float x0 = xp[0], x1 = xp[1];
    float h0 = __bfloat162float(__float2bfloat16(x0));
    float h1 = __bfloat162float(__float2bfloat16(x1));
    u32* dst = g_Xfrag[t];
    dst[((ks * 2 + 0) * 8 + n8t) * 64 + lane * 2 + reg] = packbf2(x0, x1);
    dst[((ks * 2 + 1) * 8 + n8t) * 64 + lane * 2 + reg] = packbf2(x0 - h0, x1 - h1);
}

// ---------------- prep1: Wih A-fragment images (256 blocks) -----------------
__global__ void __launch_bounds__(256) prep1_kernel(
    const float* __restrict__ Wf, const float* __restrict__ Wr)
{
    const int bg  = blockIdx.x >> 3;      // dir*16+mg
    const int sub = blockIdx.x & 7;
    const int dir = bg >> 4, mg = bg & 15;
    const float* __restrict__ W = dir ? Wr : Wf;
    u32* dst = g_P1A + (size_t)bg * 65536;
    for (int q = threadIdx.x; q < 8192; q += 256) {
        int idx = sub * 8192 + q;
        int reg = idx & 3;
        int lane = (idx >> 2) & 31;
        int ksl = (idx >> 7) & 3;
        int mt8 = (idx >> 9) & 7;
        int hl  = (idx >> 12) & 1;
        int kc  = idx >> 13;
        int g = lane >> 2, t4 = lane & 3;
        int m = mg * 128 + mt8 * 16 + g + ((reg & 1) ? 8 : 0);
        int k = kc * 64 + ksl * 16 + 2 * t4 + ((reg & 2) ? 8 : 0);
        const float* wp = W + (size_t)m * DD + k;
        float w0 = wp[0], w1 = wp[1];
        if (hl == 0) dst[idx] = packbf2(w0, w1);
        else {
            float r0 = w0 - __bfloat162float(__float2bfloat16(w0));
            float r1 = w1 - __bfloat162float(__float2bfloat16(w1));
            dst[idx] = packbf2(r0, r1);
        }
    }
}

// ---------------- phase1_mma: G = x@Wih^T + bias via mma.sync ---------------
#define P1_STAGE 65536
#define P1_BIAS  131072
#define P1_SMEM  131584

#define P1_ISSUE(c, slot) do {                                                  \
    unsigned sa = smem_u32(smem + (slot) * P1_STAGE);                           \
    const char* as = (const char*)(Abase + (size_t)(c) * 8192);                 \
    _Pragma("unroll")                                                           \
    for (int i = 0; i < 8; i++)                                                 \
        cp16(sa + (unsigned)(tid + 256 * i) * 16u, as + (size_t)(tid + 256 * i) * 16); \
    unsigned sb = sa + 32768u;                                                  \
    const char* b0 = (const char*)(B0 + (size_t)(c) * 4096);                    \
    const char* b1 = (const char*)(B1 + (size_t)(c) * 4096);                    \
    _Pragma("unroll")                                                           \
    for (int i = 0; i < 4; i++) {                                               \
        cp16(sb + (unsigned)(tid + 256 * i) * 16u, b0 + (size_t)(tid + 256 * i) * 16); \
        cp16(sb + 16384u + (unsigned)(tid + 256 * i) * 16u, b1 + (size_t)(tid + 256 * i) * 16); \
    }                                                                           \
    cp_commit();                                                                \
} while (0)

__global__ void __launch_bounds__(256) phase1_mma_kernel(
    const float* __restrict__ bif, const float* __restrict__ bhf,
    const float* __restrict__ bir, const float* __restrict__ bhr)
{
    extern __shared__ __align__(16) char smem[];
    const int tid = threadIdx.x;
    const int mg = blockIdx.x, tp = blockIdx.y, dir = blockIdx.z;
    float* bias = (float*)(smem + P1_BIAS);
    if (tid < 128) {
        int n = mg * 128 + tid;
        bias[tid] = dir ? (bir[n] + bhr[n]) : (bif[n] + bhf[n]);
    }
    const u32* Abase = g_P1A + (size_t)(dir * 16 + mg) * 65536;
    const u32* B0 = g_Xfrag[tp * 2];
    const u32* B1 = g_Xfrag[tp * 2 + 1];

    P1_ISSUE(0, 0);
    P1_ISSUE(1, 1);

    const int w = tid >> 5, lane = tid & 31;
    const int lg = lane >> 2, lt = lane & 3;
    float cf[16][4];
#pragma unroll
    for (int j = 0; j < 16; j++)
#pragma unroll
        for (int r = 0; r < 4; r++) cf[j][r] = 0.0f;

    for (int ch = 0; ch < 8; ch++) {
        if (ch == 7) cp_wait0(); else cp_wait1();
        __syncthreads();
        const char* As = smem + (ch & 1) * P1_STAGE;
        const char* Bs = As + 32768;
#pragma unroll
        for (int ksl = 0; ksl < 4; ksl++) {
            uint4 vh = *(const uint4*)(As + ((size_t)(w * 4 + ksl) * 128 + lane * 4) * 4);
            uint4 vl = *(const uint4*)(As + 16384 + ((size_t)(w * 4 + ksl) * 128 + lane * 4) * 4);
            u32 ah[4] = {vh.x, vh.y, vh.z, vh.w};
            u32 al[4] = {vl.x, vl.y, vl.z, vl.w};
#pragma unroll
            for (int j = 0; j < 16; j++) {
                const int t_loc = j >> 3, n8t = j & 7;
                const char* bb = Bs + t_loc * 16384
                    + ((size_t)((ksl * 2 + 0) * 8 + n8t) * 32 + lane) * 8;
                u64 bh = *(const u64*)bb;
                u64 bl = *(const u64*)(bb + 2048);
                mma16816(cf[j], ah, (u32)bh, (u32)(bh >> 32));
                mma16816(cf[j], al, (u32)bh, (u32)(bh >> 32));
                mma16816(cf[j], ah, (u32)bl, (u32)(bl >> 32));
            }
        }
        __syncthreads();
        if (ch + 2 < 8) P1_ISSUE(ch + 2, ch & 1);
    }

    const int r0 = mg * 128 + w * 16 + lg;
    const float bs0 = bias[w * 16 + lg];
    const float bs1 = bias[w * 16 + lg + 8];
#pragma unroll
    for (int j = 0; j < 16; j++) {
        int n = j * 8 + 2 * lt;
        int t_loc = n >> 6, b = n & 63;
        int t = tp * 2 + t_loc;
        int s = dir ? (TT - 1 - t) : t;
        float* gp = g_G + ((size_t)(dir * TT + s) * G4 + r0) * BB + b;
        *(float2*)gp = make_float2(cf[j][0] + bs0, cf[j][1] + bs0);
        *(float2*)(gp + 8 * BB) = make_float2(cf[j][2] + bs1, cf[j][3] + bs1);
    }
}

// ---------------- prep: Whh fragment images + resets ------------------------
__global__ void __launch_bounds__(256) prep_kernel(
    const float* __restrict__ Whf, const float* __restrict__ Whr)
{
    const int cid = blockIdx.x;
    const int dir = cid >> 6;
    const int j0  = (cid & 63) * 8;
    const float* __restrict__ W = dir ? Whr : Whf;
    for (int idx = threadIdx.x; idx < 16384; idx += 256) {
        int hl = idx >> 13;
        int rem = idx & 8191;
        int mt = rem >> 12;
        int ks = (rem >> 7) & 31;
        int lane = (rem >> 2) & 31;
        int reg = rem & 3;
        int g = lane >> 2, t = lane & 3;
        int m = mt * 16 + g + ((reg & 1) ? 8 : 0);
        int k = ks * 16 + 2 * t + ((reg & 2) ? 8 : 0);
        int gate = m >> 3, u = m & 7;
        const float* wr = W + (size_t)(gate * HH + j0 + u) * HH + k;
        float w0 = wr[0], w1 = wr[1];
        if (hl == 0) {
            g_Afrag[cid][idx] = packbf2(w0, w1);
        } else {
            float r0 = w0 - __bfloat162float(__float2bfloat16(w0));
            float r1 = w1 - __bfloat162float(__float2bfloat16(w1));
            g_Afrag[cid][idx] = packbf2(r0, r1);
        }
    }
    {
        int i = blockIdx.x * 256 + threadIdx.x;
        u64* Z = (u64*)&g_hfrag[0][0][0];
        if (i < 32768) Z[i] = 0ull;
    }
    if (cid == 0 && threadIdx.x < 16)
        ((unsigned*)g_rdy)[threadIdx.x] = 0;
}

// ---------------- Phase 2: dataflow-synced persistent mma recurrence --------
#define SB_AF  0
#define SB_HF  65536
#define SB_GS  196608
#define SB_DEX 205312
#define SB_CS  222208
#define SB_HS  224320
#define SB_MK  226432
#define SB_MB  226688
#define SMEM2  226816

__global__ void __launch_bounds__(256) phase2_kernel(
    const float* __restrict__ mask, float* __restrict__ out)
{
    extern __shared__ __align__(16) char smem[];
    float* Gs  = (float*)(smem + SB_GS);
    float* Dex = (float*)(smem + SB_DEX);
    float* cs  = (float*)(smem + SB_CS);
    float* hs  = (float*)(smem + SB_HS);
    float* Ms  = (float*)(smem + SB_MK);
    const unsigned af_sa = smem_u32(smem + SB_AF);
    const unsigned hf_sa = smem_u32(smem + SB_HF);
    const unsigned gs_sa = smem_u32(smem + SB_GS);
    const unsigned mk_sa = smem_u32(smem + SB_MK);
    const unsigned MB    = smem_u32(smem + SB_MB);

    const int tid = threadIdx.x;
    const int cid = blockIdx.x;
    const int dir = cid >> 6;
    const int j0  = (cid & 63) * 8;
    const int mychunk = (cid & 63) >> 3;

    if (tid < 8) mbar_init(MB + tid * 8, 1);
    for (int i = tid; i < 528; i += 256) { cs[i] = 0.0f; hs[i] = 0.0f; }
#pragma unroll
    for (int r = 0; r < 16; r++) {
        unsigned o = (unsigned)(tid + 256 * r) * 16u;
        cp16(af_sa + o, (const char*)&g_Afrag[cid][0] + o);
    }
    cp_commit();
    cp_wait0();
    __syncthreads();

    const int wid  = tid >> 5;
    const int lane = tid & 31;
    const int mt   = wid & 1;
    const int kh   = (wid >> 1) & 1;
    const int nh   = wid >> 2;
    const int lg   = lane >> 2, lt = lane & 3;

    // prologue: issue step-0 bulks, one chunk per warp (parallel)
    if (lane == 0) {
        mbar_expect_tx(MB + wid * 8, 16384u);
        bulk_g2s(hf_sa + (unsigned)wid * 16384u,
                 &g_hfrag[0][dir][wid * 4096], 16384u, MB + wid * 8);
    }

    for (int s = 0; s < TT; s++) {
        const int nb = (s & 1) ^ 1;
        const int tg = dir ? (TT - 1 - s) : s;

        // G + mask cp.async for this step (overlaps MMA)
#pragma unroll
        for (int i = 0; i < 2; i++) {
            int seg = tid + 256 * i;
            int row = seg >> 4, part = seg & 15;
            const float* src = g_G + ((size_t)(dir * TT + s) * G4
                + (row >> 3) * HH + j0 + (row & 7)) * BB + part * 4;
            cp16(gs_sa + (unsigned)(row * 272 + part * 16), src);
        }
        if (tid < 16)
            cp16(mk_sa + tid * 16, mask + (size_t)tg * BB + tid * 4);
        cp_commit();

        // ---- GEMM ----
        float c[4][4];
#pragma unroll
        for (int j = 0; j < 4; j++)
#pragma unroll
            for (int r = 0; r < 4; r++) c[j][r] = 0.0f;

#pragma unroll 4
        for (int ki = 0; ki < 16; ki++) {
            const int ks = kh * 16 + ki;
            if ((ki & 3) == 0) mbar_wait(MB + (ks >> 2) * 8, (unsigned)(s & 1));
            u32 ah[4], al[4];
            {
                uint4 v = *(const uint4*)(smem + SB_AF +
                    ((size_t)((mt * 32 + ks) * 32 + lane)) * 16);
                ah[0] = v.x; ah[1] = v.y; ah[2] = v.z; ah[3] = v.w;
                uint4 w2 = *(const uint4*)(smem + SB_AF + 65536 / 2 +
                    ((size_t)((mt * 32 + ks) * 32 + lane)) * 16);
                al[0] = w2.x; al[1] = w2.y; al[2] = w2.z; al[3] = w2.w;
            }
#pragma unroll
            for (int j = 0; j < 4; j++) {
                const int n8t = nh * 4 + j;
                const char* bb = smem + SB_HF +
                    ((size_t)((ks * 2 + 0) * 8 + n8t) * 32 + lane) * 8;
                u64 bh = *(const u64*)bb;
                u64 bl = *(const u64*)(bb + 512 * 4);
                u32 bh0 = (u32)bh, bh1 = (u32)(bh >> 32);
                u32 bl0 = (u32)bl, bl1 = (u32)(bl >> 32);
                mma16816(c[j], ah, bh0, bh1);
                mma16816(c[j], al, bh0, bh1);
                mma16816(c[j], ah, bl0, bl1);
            }
        }

        {
            float* dp = Dex + kh * 2112;
            const int row0 = mt * 16 + lg;
#pragma unroll
            for (int j = 0; j < 4; j++) {
                const int col = (nh * 4 + j) * 8 + 2 * lt;
                *(float2*)&dp[row0 * 66 + col]       = make_float2(c[j][0], c[j][1]);
                *(float2*)&dp[(row0 + 8) * 66 + col] = make_float2(c[j][2], c[j][3]);
            }
        }
        cp_wait0();
        __syncthreads();

        // ---- epilogue: publish h first, then signal, then out store ----
        float hn[2];
        const int b = tid & 63;
        const int u0 = (tid >> 6) * 2;
        {
            const float m = Ms[b];
#pragma unroll
            for (int q = 0; q < 2; q++) {
                const int u = u0 + q;
                float pi = Dex[u * 66 + b]        + Dex[2112 + u * 66 + b]        + Gs[u * 68 + b];
                float pf = Dex[(8 + u) * 66 + b]  + Dex[2112 + (8 + u) * 66 + b]  + Gs[(8 + u) * 68 + b];
                float pg = Dex[(16 + u) * 66 + b] + Dex[2112 + (16 + u) * 66 + b] + Gs[(16 + u) * 68 + b];
                float po = Dex[(24 + u) * 66 + b] + Dex[2112 + (24 + u) * 66 + b] + Gs[(24 + u) * 68 + b];
                float ig = sigf(pi), fg = sigf(pf);
                float gg = tanhfast(pg), og = sigf(po);
                float c_old = cs[u * 66 + b];
                float c2 = fg * c_old + ig * gg;
                float h2 = og * tanhfast(c2);
                float c_new = c_old + m * (c2 - c_old);
                float h_old = hs[u * 66 + b];
                float h_new = h_old + m * (h2 - h_old);
                cs[u * 66 + b] = c_new;
                hs[u * 66 + b] = h_new;
                hn[q] = h_new;
            }
            float b0h = __bfloat162float(__float2bfloat16(hn[0]));
            float b1h = __bfloat162float(__float2bfloat16(hn[1]));
            u32 hi = packbf2(hn[0], hn[1]);
            u32 lo = packbf2(hn[0] - b0h, hn[1] - b1h);
            const int ks2 = j0 >> 4;
            const int reg = (j0 & 15) >> 3;
            const int n8t = b >> 3;
            const int lane2 = (b & 7) * 4 + (u0 >> 1);
            u32* dst = &g_hfrag[nb][dir][((ks2 * 2 + 0) * 8 + n8t) * 64 + lane2 * 2 + reg];
            dst[0]   = hi;
            dst[512] = lo;
        }
        __threadfence();
        __syncthreads();
        if (tid == 0) atomicAdd(&g_rdy[dir][mychunk], 1u);

        // loader for step s+1: one chunk per warp, parallel spins
        if (s + 1 < TT && lane == 0) {
            const unsigned target = 8u * (unsigned)(s + 1);
            while (*(volatile unsigned*)&g_rdy[dir][wid] < target) { }
            mbar_expect_tx(MB + wid * 8, 16384u);
            bulk_g2s(hf_sa + (unsigned)wid * 16384u,
                     &g_hfrag[nb][dir][wid * 4096], 16384u, MB + wid * 8);
        }

        // output store
        *(float2*)&out[(size_t)tg * (BB * 1024) + (size_t)b * 1024
                       + dir * HH + j0 + u0] = make_float2(hn[0], hn[1]);
    }
}

// ---------------- Launch ----------------
extern "C" void kernel_launch(void* const* d_in, const int* in_sizes, int n_in,
                              void* d_out, int out_size) {
    const float* x_data = (const float*)d_in[0];
    const float* x_mask = (const float*)d_in[1];
    const float* Wih_f  = (const float*)d_in[2];
    const float* Whh_f  = (const float*)d_in[3];
    const float* bih_f  = (const float*)d_in[4];
    const float* bhh_f  = (const float*)d_in[5];
    const float* Wih_r  = (const float*)d_in[6];
    const float* Whh_r  = (const float*)d_in[7];
    const float* bih_r  = (const float*)d_in[8];
    const float* bhh_r  = (const float*)d_in[9];
    float* out = (float*)d_out;

    static bool attr_set = false;
    if (!attr_set) {
        cudaFuncSetAttribute(phase2_kernel,
                             cudaFuncAttributeMaxDynamicSharedMemorySize, SMEM2);
        cudaFuncSetAttribute(phase1_mma_kernel,
                             cudaFuncAttributeMaxDynamicSharedMemorySize, P1_SMEM);
        attr_set = true;
    }
    xconv_kernel<<<32768, 256>>>(x_data);
    prep1_kernel<<<256, 256>>>(Wih_f, Wih_r);
    prep_kernel<<<NCTA, 256>>>(Whh_f, Whh_r);
    phase1_mma_kernel<<<dim3(16, 256, 2), 256, P1_SMEM>>>(bih_f, bhh_f, bih_r, bhh_r);
    phase2_kernel<<<NCTA, 256, SMEM2>>>(x_mask, out);
}

// round 15
// speedup vs baseline: 2.9279x; 1.0541x over previous
#include <cuda_runtime.h>
#include <cuda_bf16.h>
#include <cstdint>

typedef unsigned long long u64;
typedef unsigned u32;

#define TT 512
#define BB 64
#define DD 512
#define HH 512
#define G4 2048
#define NCTA 128

// ---------------- global scratch ----------------
__device__ float g_G[(size_t)2 * TT * G4 * BB];   // x@Wih^T + bias
__device__ u32 g_Afrag[NCTA][16384];              // Whh frags (phase2)
__device__ u32 g_hfrag[2][2][32768];              // h frags (phase2)
__device__ u32 g_Xfrag[TT][32768];                // x frags (phase1 B)
__device__ u32 g_P1A[2097152];                    // Wih frags (phase1 A) 8MB
__device__ unsigned g_rdy[2][8];                  // per (dir, chunk) publish counters

// ---------------- helpers ----------------
__device__ __forceinline__ float sigf(float x)  { return 1.0f / (1.0f + __expf(-x)); }
__device__ __forceinline__ float tanhfast(float x) {
    return 2.0f / (1.0f + __expf(-2.0f * x)) - 1.0f;
}
__device__ __forceinline__ unsigned smem_u32(const void* p) {
    return (unsigned)__cvta_generic_to_shared(p);
}
__device__ __forceinline__ void cp16(unsigned dst, const void* src) {
    asm volatile("cp.async.cg.shared.global [%0], [%1], 16;" :: "r"(dst), "l"(src) : "memory");
}
__device__ __forceinline__ void cp_commit() { asm volatile("cp.async.commit_group;" ::: "memory"); }
__device__ __forceinline__ void cp_wait0()  { asm volatile("cp.async.wait_group 0;" ::: "memory"); }
__device__ __forceinline__ void cp_wait1()  { asm volatile("cp.async.wait_group 1;" ::: "memory"); }

__device__ __forceinline__ void mbar_init(unsigned a, unsigned c) {
    asm volatile("mbarrier.init.shared.b64 [%0], %1;" :: "r"(a), "r"(c) : "memory");
}
__device__ __forceinline__ void mbar_expect_tx(unsigned a, unsigned b) {
    asm volatile("mbarrier.arrive.expect_tx.shared.b64 _, [%0], %1;" :: "r"(a), "r"(b) : "memory");
}
__device__ __forceinline__ void bulk_g2s(unsigned dst, const void* src, unsigned bytes, unsigned mb) {
    asm volatile("cp.async.bulk.shared::cta.global.mbarrier::complete_tx::bytes [%0], [%1], %2, [%3];"
                 :: "r"(dst), "l"(src), "r"(bytes), "r"(mb) : "memory");
}
__device__ __forceinline__ void mbar_wait(unsigned a, unsigned par) {
    asm volatile(
        "{\n\t.reg .pred P;\n\t"
        "WL_%=:\n\t"
        "mbarrier.try_wait.parity.acquire.cta.shared::cta.b64 P, [%0], %1, 0x989680;\n\t"
        "@P bra.uni WD_%=;\n\t"
        "bra.uni WL_%=;\n\t"
        "WD_%=:\n\t}"
        :: "r"(a), "r"(par) : "memory");
}

__device__ __forceinline__ void mma16816(float* c, const u32* a, u32 b0, u32 b1) {
    asm volatile(
        "mma.sync.aligned.m16n8k16.row.col.f32.bf16.bf16.f32 "
        "{%0,%1,%2,%3}, {%4,%5,%6,%7}, {%8,%9}, {%0,%1,%2,%3};"
        : "+f"(c[0]), "+f"(c[1]), "+f"(c[2]), "+f"(c[3])
        : "r"(a[0]), "r"(a[1]), "r"(a[2]), "r"(a[3]), "r"(b0), "r"(b1));
}
__device__ __forceinline__ u32 packbf2(float e0, float e1) {
    __nv_bfloat162 v = __float22bfloat162_rn(make_float2(e0, e1));
    return *(u32*)&v;
}

// ---------------- xconv: x -> B-fragment images (same layout as h frags) ----
__global__ void __launch_bounds__(256) xconv_kernel(const float* __restrict__ x)
{
    int idx = blockIdx.x * 256 + threadIdx.x;    // 8,388,608
    int reg = idx & 1;
    int lane = (idx >> 1) & 31;
    int n8t = (idx >> 6) & 7;
    int ks  = (idx >> 9) & 31;
    int t   = idx >> 14;
    int g = lane >> 2, t4 = lane & 3;
    int b = n8t * 8 + g;
    int k = ks * 16 + reg * 8 + t4 * 2;
    const float* xp = x + ((size_t)t * BB + b) * DD + k;
    float x0 = xp[0], x1 = xp[1];
    float h0 = __bfloat162float(__float2bfloat16(x0));
    float h1 = __bfloat162float(__float2bfloat16(x1));
    u32* dst = g_Xfrag[t];
    dst[((ks * 2 + 0) * 8 + n8t) * 64 + lane * 2 + reg] = packbf2(x0, x1);
    dst[((ks * 2 + 1) * 8 + n8t) * 64 + lane * 2 + reg] = packbf2(x0 - h0, x1 - h1);
}

// ---------------- prep1: Wih A-fragment images (256 blocks) -----------------
__global__ void __launch_bounds__(256) prep1_kernel(
    const float* __restrict__ Wf, const float* __restrict__ Wr)
{
    const int bg  = blockIdx.x >> 3;      // dir*16+mg
    const int sub = blockIdx.x & 7;
    const int dir = bg >> 4, mg = bg & 15;
    const float* __restrict__ W = dir ? Wr : Wf;
    u32* dst = g_P1A + (size_t)bg * 65536;
    for (int q = threadIdx.x; q < 8192; q += 256) {
        int idx = sub * 8192 + q;
        int reg = idx & 3;
        int lane = (idx >> 2) & 31;
        int ksl = (idx >> 7) & 3;
        int mt8 = (idx >> 9) & 7;
        int hl  = (idx >> 12) & 1;
        int kc  = idx >> 13;
        int g = lane >> 2, t4 = lane & 3;
        int m = mg * 128 + mt8 * 16 + g + ((reg & 1) ? 8 : 0);
        int k = kc * 64 + ksl * 16 + 2 * t4 + ((reg & 2) ? 8 : 0);
        const float* wp = W + (size_t)m * DD + k;
        float w0 = wp[0], w1 = wp[1];
        if (hl == 0) dst[idx] = packbf2(w0, w1);
        else {
            float r0 = w0 - __bfloat162float(__float2bfloat16(w0));
            float r1 = w1 - __bfloat162float(__float2bfloat16(w1));
            dst[idx] = packbf2(r0, r1);
        }
    }
}

// ---------------- phase1_mma: G = x@Wih^T + bias via mma.sync ---------------
#define P1_STAGE 65536
#define P1_BIAS  131072
#define P1_SMEM  131584

#define P1_ISSUE(c, slot) do {                                                  \
    unsigned sa = smem_u32(smem + (slot) * P1_STAGE);                           \
    const char* as = (const char*)(Abase + (size_t)(c) * 8192);                 \
    _Pragma("unroll")                                                           \
    for (int i = 0; i < 8; i++)                                                 \
        cp16(sa + (unsigned)(tid + 256 * i) * 16u, as + (size_t)(tid + 256 * i) * 16); \
    unsigned sb = sa + 32768u;                                                  \
    const char* b0 = (const char*)(B0 + (size_t)(c) * 4096);                    \
    const char* b1 = (const char*)(B1 + (size_t)(c) * 4096);                    \
    _Pragma("unroll")                                                           \
    for (int i = 0; i < 4; i++) {                                               \
        cp16(sb + (unsigned)(tid + 256 * i) * 16u, b0 + (size_t)(tid + 256 * i) * 16); \
        cp16(sb + 16384u + (unsigned)(tid + 256 * i) * 16u, b1 + (size_t)(tid + 256 * i) * 16); \
    }                                                                           \
    cp_commit();                                                                \
} while (0)

__global__ void __launch_bounds__(256) phase1_mma_kernel(
    const float* __restrict__ bif, const float* __restrict__ bhf,
    const float* __restrict__ bir, const float* __restrict__ bhr)
{
    extern __shared__ __align__(16) char smem[];
    const int tid = threadIdx.x;
    const int mg = blockIdx.x, tp = blockIdx.y, dir = blockIdx.z;
    float* bias = (float*)(smem + P1_BIAS);
    if (tid < 128) {
        int n = mg * 128 + tid;
        bias[tid] = dir ? (bir[n] + bhr[n]) : (bif[n] + bhf[n]);
    }
    const u32* Abase = g_P1A + (size_t)(dir * 16 + mg) * 65536;
    const u32* B0 = g_Xfrag[tp * 2];
    const u32* B1 = g_Xfrag[tp * 2 + 1];

    P1_ISSUE(0, 0);
    P1_ISSUE(1, 1);

    const int w = tid >> 5, lane = tid & 31;
    const int lg = lane >> 2, lt = lane & 3;
    float cf[16][4];
#pragma unroll
    for (int j = 0; j < 16; j++)
#pragma unroll
        for (int r = 0; r < 4; r++) cf[j][r] = 0.0f;

    for (int ch = 0; ch < 8; ch++) {
        if (ch == 7) cp_wait0(); else cp_wait1();
        __syncthreads();
        const char* As = smem + (ch & 1) * P1_STAGE;
        const char* Bs = As + 32768;
#pragma unroll
        for (int ksl = 0; ksl < 4; ksl++) {
            uint4 vh = *(const uint4*)(As + ((size_t)(w * 4 + ksl) * 128 + lane * 4) * 4);
            uint4 vl = *(const uint4*)(As + 16384 + ((size_t)(w * 4 + ksl) * 128 + lane * 4) * 4);
            u32 ah[4] = {vh.x, vh.y, vh.z, vh.w};
            u32 al[4] = {vl.x, vl.y, vl.z, vl.w};
#pragma unroll
            for (int j = 0; j < 16; j++) {
                const int t_loc = j >> 3, n8t = j & 7;
                const char* bb = Bs + t_loc * 16384
                    + ((size_t)((ksl * 2 + 0) * 8 + n8t) * 32 + lane) * 8;
                u64 bh = *(const u64*)bb;
                u64 bl = *(const u64*)(bb + 2048);
                mma16816(cf[j], ah, (u32)bh, (u32)(bh >> 32));
                mma16816(cf[j], al, (u32)bh, (u32)(bh >> 32));
                mma16816(cf[j], ah, (u32)bl, (u32)(bl >> 32));
            }
        }
        __syncthreads();
        if (ch + 2 < 8) P1_ISSUE(ch + 2, ch & 1);
    }

    const int r0 = mg * 128 + w * 16 + lg;
    const float bs0 = bias[w * 16 + lg];
    const float bs1 = bias[w * 16 + lg + 8];
#pragma unroll
    for (int j = 0; j < 16; j++) {
        int n = j * 8 + 2 * lt;
        int t_loc = n >> 6, b = n & 63;
        int t = tp * 2 + t_loc;
        int s = dir ? (TT - 1 - t) : t;
        float* gp = g_G + ((size_t)(dir * TT + s) * G4 + r0) * BB + b;
        *(float2*)gp = make_float2(cf[j][0] + bs0, cf[j][1] + bs0);
        *(float2*)(gp + 8 * BB) = make_float2(cf[j][2] + bs1, cf[j][3] + bs1);
    }
}

// ---------------- prep: Whh fragment images + resets ------------------------
__global__ void __launch_bounds__(256) prep_kernel(
    const float* __restrict__ Whf, const float* __restrict__ Whr)
{
    const int cid = blockIdx.x;
    const int dir = cid >> 6;
    const int j0  = (cid & 63) * 8;
    const float* __restrict__ W = dir ? Whr : Whf;
    for (int idx = threadIdx.x; idx < 16384; idx += 256) {
        int hl = idx >> 13;
        int rem = idx & 8191;
        int mt = rem >> 12;
        int ks = (rem >> 7) & 31;
        int lane = (rem >> 2) & 31;
        int reg = rem & 3;
        int g = lane >> 2, t = lane & 3;
        int m = mt * 16 + g + ((reg & 1) ? 8 : 0);
        int k = ks * 16 + 2 * t + ((reg & 2) ? 8 : 0);
        int gate = m >> 3, u = m & 7;
        const float* wr = W + (size_t)(gate * HH + j0 + u) * HH + k;
        float w0 = wr[0], w1 = wr[1];
        if (hl == 0) {
            g_Afrag[cid][idx] = packbf2(w0, w1);
        } else {
            float r0 = w0 - __bfloat162float(__float2bfloat16(w0));
            float r1 = w1 - __bfloat162float(__float2bfloat16(w1));
            g_Afrag[cid][idx] = packbf2(r0, r1);
        }
    }
    {
        int i = blockIdx.x * 256 + threadIdx.x;
        u64* Z = (u64*)&g_hfrag[0][0][0];
        if (i < 32768) Z[i] = 0ull;
    }
    if (cid == 0 && threadIdx.x < 16)
        ((unsigned*)g_rdy)[threadIdx.x] = 0;
}

// ---------------- Phase 2: dataflow-synced persistent mma recurrence --------
#define SB_AF  0
#define SB_HF  65536
#define SB_DEX 205312
#define SB_CS  222208
#define SB_HS  224320
#define SB_MB  226688
#define SMEM2  226816

__global__ void __launch_bounds__(256) phase2_kernel(
    const float* __restrict__ mask, float* __restrict__ out)
{
    extern __shared__ __align__(16) char smem[];
    float* Dex = (float*)(smem + SB_DEX);
    float* cs  = (float*)(smem + SB_CS);
    float* hs  = (float*)(smem + SB_HS);
    const unsigned af_sa = smem_u32(smem + SB_AF);
    const unsigned hf_sa = smem_u32(smem + SB_HF);
    const unsigned MB    = smem_u32(smem + SB_MB);

    const int tid = threadIdx.x;
    const int cid = blockIdx.x;
    const int dir = cid >> 6;
    const int j0  = (cid & 63) * 8;
    const int mychunk = (cid & 63) >> 3;

    if (tid < 8) mbar_init(MB + tid * 8, 1);
    for (int i = tid; i < 528; i += 256) { cs[i] = 0.0f; hs[i] = 0.0f; }
#pragma unroll
    for (int r = 0; r < 16; r++) {
        unsigned o = (unsigned)(tid + 256 * r) * 16u;
        cp16(af_sa + o, (const char*)&g_Afrag[cid][0] + o);
    }
    cp_commit();
    cp_wait0();
    __syncthreads();

    const int wid  = tid >> 5;
    const int lane = tid & 31;
    const int mt   = wid & 1;
    const int kh   = (wid >> 1) & 1;
    const int nh   = wid >> 2;
    const int lg   = lane >> 2, lt = lane & 3;
    const int b    = tid & 63;
    const int u0   = (tid >> 6) * 2;

    // prologue: issue step-0 bulks, one chunk per warp (parallel)
    if (lane == 0) {
        mbar_expect_tx(MB + wid * 8, 16384u);
        bulk_g2s(hf_sa + (unsigned)wid * 16384u,
                 &g_hfrag[0][dir][wid * 4096], 16384u, MB + wid * 8);
    }

    for (int s = 0; s < TT; s++) {
        const int nb = (s & 1) ^ 1;
        const int tg = dir ? (TT - 1 - s) : s;

        // G + mask prefetch into REGISTERS (consumed in epilogue; fully hidden)
        float gv[2][4];
        {
            const float* gbase = g_G + ((size_t)(dir * TT + s) * G4) * BB + b;
#pragma unroll
            for (int q = 0; q < 2; q++) {
                const int u = u0 + q;
#pragma unroll
                for (int g = 0; g < 4; g++)
                    gv[q][g] = __ldg(gbase + (size_t)(g * HH + j0 + u) * BB);
            }
        }
        const float m = __ldg(mask + (size_t)tg * BB + b);

        // ---- GEMM: interleaved chunk striping (kh half rides early chunks) ----
        float c[4][4];
#pragma unroll
        for (int j = 0; j < 4; j++)
#pragma unroll
            for (int r = 0; r < 4; r++) c[j][r] = 0.0f;

#pragma unroll 4
        for (int ki = 0; ki < 16; ki++) {
            const int ks = (ki >> 2) * 8 + kh * 4 + (ki & 3);
            if ((ki & 3) == 0) mbar_wait(MB + ((ki >> 2) * 2 + kh) * 8, (unsigned)(s & 1));
            u32 ah[4], al[4];
            {
                uint4 v = *(const uint4*)(smem + SB_AF +
                    ((size_t)((mt * 32 + ks) * 32 + lane)) * 16);
                ah[0] = v.x; ah[1] = v.y; ah[2] = v.z; ah[3] = v.w;
                uint4 w2 = *(const uint4*)(smem + SB_AF + 65536 / 2 +
                    ((size_t)((mt * 32 + ks) * 32 + lane)) * 16);
                al[0] = w2.x; al[1] = w2.y; al[2] = w2.z; al[3] = w2.w;
            }
#pragma unroll
            for (int j = 0; j < 4; j++) {
                const int n8t = nh * 4 + j;
                const char* bb = smem + SB_HF +
                    ((size_t)((ks * 2 + 0) * 8 + n8t) * 32 + lane) * 8;
                u64 bh = *(const u64*)bb;
                u64 bl = *(const u64*)(bb + 512 * 4);
                u32 bh0 = (u32)bh, bh1 = (u32)(bh >> 32);
                u32 bl0 = (u32)bl, bl1 = (u32)(bl >> 32);
                mma16816(c[j], ah, bh0, bh1);
                mma16816(c[j], al, bh0, bh1);
                mma16816(c[j], ah, bl0, bl1);
            }
        }

        {
            float* dp = Dex + kh * 2112;
            const int row0 = mt * 16 + lg;
#pragma unroll
            for (int j = 0; j < 4; j++) {
                const int col = (nh * 4 + j) * 8 + 2 * lt;
                *(float2*)&dp[row0 * 66 + col]       = make_float2(c[j][0], c[j][1]);
                *(float2*)&dp[(row0 + 8) * 66 + col] = make_float2(c[j][2], c[j][3]);
            }
        }
        __syncthreads();

        // ---- epilogue: publish h first, then signal, then out store ----
        float hn[2];
        {
#pragma unroll
            for (int q = 0; q < 2; q++) {
                const int u = u0 + q;
                float pi = Dex[u * 66 + b]        + Dex[2112 + u * 66 + b]        + gv[q][0];
                float pf = Dex[(8 + u) * 66 + b]  + Dex[2112 + (8 + u) * 66 + b]  + gv[q][1];
                float pg = Dex[(16 + u) * 66 + b] + Dex[2112 + (16 + u) * 66 + b] + gv[q][2];
                float po = Dex[(24 + u) * 66 + b] + Dex[2112 + (24 + u) * 66 + b] + gv[q][3];
                float ig = sigf(pi), fg = sigf(pf);
                float gg = tanhfast(pg), og = sigf(po);
                float c_old = cs[u * 66 + b];
                float c2 = fg * c_old + ig * gg;
                float h2 = og * tanhfast(c2);
                float c_new = c_old + m * (c2 - c_old);
                float h_old = hs[u * 66 + b];
                float h_new = h_old + m * (h2 - h_old);
                cs[u * 66 + b] = c_new;
                hs[u * 66 + b] = h_new;
                hn[q] = h_new;
            }
            float b0h = __bfloat162float(__float2bfloat16(hn[0]));
            float b1h = __bfloat162float(__float2bfloat16(hn[1]));
            u32 hi = packbf2(hn[0], hn[1]);
            u32 lo = packbf2(hn[0] - b0h, hn[1] - b1h);
            const int ks2 = j0 >> 4;
            const int reg = (j0 & 15) >> 3;
            const int n8t = b >> 3;
            const int lane2 = (b & 7) * 4 + (u0 >> 1);
            u32* dst = &g_hfrag[nb][dir][((ks2 * 2 + 0) * 8 + n8t) * 64 + lane2 * 2 + reg];
            dst[0]   = hi;
            dst[512] = lo;
        }
        __threadfence();
        __syncthreads();
        if (tid == 0) atomicAdd(&g_rdy[dir][mychunk], 1u);

        // loader for step s+1: one chunk per warp, parallel spins
        if (s + 1 < TT && lane == 0) {
            const unsigned target = 8u * (unsigned)(s + 1);
            while (*(volatile unsigned*)&g_rdy[dir][wid] < target) { }
            mbar_expect_tx(MB + wid * 8, 16384u);
            bulk_g2s(hf_sa + (unsigned)wid * 16384u,
                     &g_hfrag[nb][dir][wid * 4096], 16384u, MB + wid * 8);
        }

        // output store
        *(float2*)&out[(size_t)tg * (BB * 1024) + (size_t)b * 1024
                       + dir * HH + j0 + u0] = make_float2(hn[0], hn[1]);
    }
}

// ---------------- Launch ----------------
extern "C" void kernel_launch(void* const* d_in, const int* in_sizes, int n_in,
                              void* d_out, int out_size) {
    const float* x_data = (const float*)d_in[0];
    const float* x_mask = (const float*)d_in[1];
    const float* Wih_f  = (const float*)d_in[2];
    const float* Whh_f  = (const float*)d_in[3];
    const float* bih_f  = (const float*)d_in[4];
    const float* bhh_f  = (const float*)d_in[5];
    const float* Wih_r  = (const float*)d_in[6];
    const float* Whh_r  = (const float*)d_in[7];
    const float* bih_r  = (const float*)d_in[8];
    const float* bhh_r  = (const float*)d_in[9];
    float* out = (float*)d_out;

    static bool attr_set = false;
    if (!attr_set) {
        cudaFuncSetAttribute(phase2_kernel,
                             cudaFuncAttributeMaxDynamicSharedMemorySize, SMEM2);
        cudaFuncSetAttribute(phase1_mma_kernel,
                             cudaFuncAttributeMaxDynamicSharedMemorySize, P1_SMEM);
        attr_set = true;
    }
    xconv_kernel<<<32768, 256>>>(x_data);
    prep1_kernel<<<256, 256>>>(Wih_f, Wih_r);
    prep_kernel<<<NCTA, 256>>>(Whh_f, Whh_r);
    phase1_mma_kernel<<<dim3(16, 256, 2), 256, P1_SMEM>>>(bih_f, bhh_f, bih_r, bhh_r);
    phase2_kernel<<<NCTA, 256, SMEM2>>>(x_mask, out);
}